// round 3
// baseline (speedup 1.0000x reference)
#include <cuda_runtime.h>
#include <math.h>

#define N_    100000
#define E_    1600000
#define ZMIX  0.8f
#define NEG   0.2f
#define EPSN  1e-5

// ---------------- device scratch (static globals; no allocation) ----------------
__device__ float  g_xp [(size_t)N_ * 128];
__device__ float  g_out[(size_t)N_ * 128];
__device__ float  g_asrc[N_];
__device__ float  g_adst[N_];
__device__ int    g_deg[N_];
__device__ int    g_off[N_ + 1];
__device__ int    g_cursor[N_];
__device__ int    g_col[E_ + N_];
__device__ int    g_bsum[128];
__device__ double g_colsum[128];
__device__ double g_colsq[128];
__device__ float  g_nscale[128];
__device__ float  g_nshift[128];
__device__ int    g_ei64;    // 1 if edge_index stored as int64, 0 if int32
__device__ int    g_mask4;   // 1 if mask stored as 4-byte words, 0 if bytes

// ---------------- dtype detection (runs first, one warp) ----------------
__global__ void k_detect(const void* ei, const void* mask) {
    int lane = threadIdx.x;
    // edge_index: if int64 with values < 2^31, every odd int32 word is 0.
    const int* w = (const int*)ei;
    int nz = 0;
    for (int k = lane; k < 512; k += 32) nz |= (w[2 * k + 1] != 0);
    // mask: sample byte offsets != 0 mod 4 within first 100000 bytes.
    // uint8 mask (p=0.5 ones) -> nonzero hits; int32/float32 bool -> all zero there.
    const unsigned char* mb = (const unsigned char*)mask;
    int mnz = 0;
    for (int k = lane; k < 500; k += 32) {
        int o = k * 196 + (k % 3) + 1;   // o in [1, 97807), o % 4 in {1,2,3}
        mnz |= (mb[o] != 0);
    }
    nz  = __any_sync(0xffffffffu, nz);
    mnz = __any_sync(0xffffffffu, mnz);
    if (lane == 0) { g_ei64 = !nz; g_mask4 = !mnz; }
}

__device__ __forceinline__ int ld_ei(const void* ei, size_t idx) {
    long long v = g_ei64 ? ((const long long*)ei)[idx]
                         : (long long)((const int*)ei)[idx];
    int t = (int)v;
    if (t < 0) t = 0;
    if (t >= N_) t = N_ - 1;
    return t;
}

__device__ __forceinline__ int ld_mask(const void* m, int i) {
    // 4-byte path covers both int32 (1) and float32 (0x3F800000): nonzero word == true
    return g_mask4 ? (((const int*)m)[i] != 0) : (((const unsigned char*)m)[i] != 0);
}

// ---------------- CSR build ----------------
__global__ void k_zero() {
    int i = blockIdx.x * blockDim.x + threadIdx.x;
    if (i < N_) g_deg[i] = 1;             // self loop
    if (i < 128) { g_colsum[i] = 0.0; g_colsq[i] = 0.0; }
}

__global__ void k_hist(const void* __restrict__ ei) {
    int e = blockIdx.x * blockDim.x + threadIdx.x;
    if (e < E_) atomicAdd(&g_deg[ld_ei(ei, (size_t)E_ + e)], 1);
}

__global__ void k_scan1() {
    __shared__ int s[1024];
    int tid = threadIdx.x;
    int g = blockIdx.x * 1024 + tid;
    int v = (g < N_) ? g_deg[g] : 0;
    s[tid] = v;
    __syncthreads();
    for (int o = 1; o < 1024; o <<= 1) {
        int t = (tid >= o) ? s[tid - o] : 0;
        __syncthreads();
        s[tid] += t;
        __syncthreads();
    }
    if (g < N_) g_off[g] = s[tid] - v;           // exclusive
    if (tid == 1023) g_bsum[blockIdx.x] = s[1023];
}

__global__ void k_scan2(int nb) {
    if (threadIdx.x == 0) {
        int r = 0;
        for (int b = 0; b < nb; b++) { int t = g_bsum[b]; g_bsum[b] = r; r += t; }
    }
}

__global__ void k_scan3() {
    int tid = threadIdx.x;
    int g = blockIdx.x * 1024 + tid;
    if (g < N_) g_off[g] += g_bsum[blockIdx.x];
    if (g == 0) g_off[N_] = N_ + E_;
}

__global__ void k_fillself() {
    int i = blockIdx.x * blockDim.x + threadIdx.x;
    if (i < N_) { int o = g_off[i]; g_col[o] = i; g_cursor[i] = o + 1; }
}

__global__ void k_filledges(const void* __restrict__ ei) {
    int e = blockIdx.x * blockDim.x + threadIdx.x;
    if (e < E_) {
        int d = ld_ei(ei, (size_t)E_ + e);
        int p = atomicAdd(&g_cursor[d], 1);
        g_col[p] = ld_ei(ei, e);
    }
}

// ---------------- fused node GEMM: x = mix(relu(xW1),relu(xW0)); xp = x*gatW^T; a_src/a_dst ----------------
// smem: As 64x132, Xb 64x132, Wt 128x132 (transposed, Wt[k*132+j]), att vecs, cz
#define SMEM_NODE ((64 * 132 * 2 + 128 * 132 + 128 + 128 + 64) * 4)

__device__ __forceinline__ void gemm128(const float* __restrict__ A, const float* __restrict__ Wt,
                                        float acc[4][8], int n0, int j0) {
#pragma unroll 4
    for (int k = 0; k < 128; ++k) {
        float4 w0 = *(const float4*)(Wt + k * 132 + j0);
        float4 w1 = *(const float4*)(Wt + k * 132 + j0 + 4);
        float w[8] = {w0.x, w0.y, w0.z, w0.w, w1.x, w1.y, w1.z, w1.w};
        float a[4];
#pragma unroll
        for (int i = 0; i < 4; ++i) a[i] = A[(n0 + i) * 132 + k];
#pragma unroll
        for (int i = 0; i < 4; ++i)
#pragma unroll
            for (int u = 0; u < 8; ++u) acc[i][u] = fmaf(a[i], w[u], acc[i][u]);
    }
}

__global__ __launch_bounds__(256, 1) void k_node(
    const float* __restrict__ x,
    const float* __restrict__ Wt0g, const float* __restrict__ bt0,
    const float* __restrict__ Wt1g, const float* __restrict__ bt1,
    const float* __restrict__ gWg,
    const float* __restrict__ atts, const float* __restrict__ attd,
    const void* __restrict__ mask)
{
    extern __shared__ float sm[];
    float* As  = sm;
    float* Xb  = As + 64 * 132;
    float* Wt  = Xb + 64 * 132;
    float* sAS = Wt + 128 * 132;
    float* sAD = sAS + 128;
    float* cz  = sAD + 128;

    int tid = threadIdx.x;
    int row0 = blockIdx.x * 64;

    for (int i = tid; i < 64 * 128; i += 256) {
        int n = i >> 7, k = i & 127;
        int gn = row0 + n;
        As[n * 132 + k] = (gn < N_) ? x[(size_t)gn * 128 + k] : 0.f;
    }
    if (tid < 128) { sAS[tid] = atts[tid]; sAD[tid] = attd[tid]; }
    if (tid < 64) {
        int gn = row0 + tid;
        cz[tid] = (gn < N_ && ld_mask(mask, gn)) ? ZMIX : (1.f - ZMIX);
    }
    for (int i = tid; i < 16384; i += 256) {
        int j = i >> 7, k = i & 127;
        Wt[k * 132 + j] = Wt1g[i];
    }
    __syncthreads();

    int ty = tid >> 4, tx = tid & 15;
    int n0 = ty * 4, j0 = tx * 8;
    float acc[4][8];

    // phase A: h1 = x*W_t1^T + b1
    {
        float bb[8];
#pragma unroll
        for (int u = 0; u < 8; ++u) bb[u] = bt1[j0 + u];
#pragma unroll
        for (int i = 0; i < 4; ++i)
#pragma unroll
            for (int u = 0; u < 8; ++u) acc[i][u] = bb[u];
    }
    gemm128(As, Wt, acc, n0, j0);
#pragma unroll
    for (int i = 0; i < 4; ++i) {
        float c = cz[n0 + i];
#pragma unroll
        for (int u = 0; u < 8; ++u)
            Xb[(n0 + i) * 132 + j0 + u] = c * fmaxf(acc[i][u], 0.f);
    }
    __syncthreads();

    // phase B: h0 = x*W_t0^T + b0 ; Xb += (1-c)*relu(h0)
    for (int i = tid; i < 16384; i += 256) {
        int j = i >> 7, k = i & 127;
        Wt[k * 132 + j] = Wt0g[i];
    }
    __syncthreads();
    {
        float bb[8];
#pragma unroll
        for (int u = 0; u < 8; ++u) bb[u] = bt0[j0 + u];
#pragma unroll
        for (int i = 0; i < 4; ++i)
#pragma unroll
            for (int u = 0; u < 8; ++u) acc[i][u] = bb[u];
    }
    gemm128(As, Wt, acc, n0, j0);
#pragma unroll
    for (int i = 0; i < 4; ++i) {
        float c = 1.f - cz[n0 + i];
#pragma unroll
        for (int u = 0; u < 8; ++u)
            Xb[(n0 + i) * 132 + j0 + u] += c * fmaxf(acc[i][u], 0.f);
    }
    __syncthreads();

    // phase C: xp = Xb * gatW^T
    for (int i = tid; i < 16384; i += 256) {
        int j = i >> 7, k = i & 127;
        Wt[k * 132 + j] = gWg[i];
    }
    __syncthreads();
#pragma unroll
    for (int i = 0; i < 4; ++i)
#pragma unroll
        for (int u = 0; u < 8; ++u) acc[i][u] = 0.f;
    gemm128(Xb, Wt, acc, n0, j0);

#pragma unroll
    for (int i = 0; i < 4; ++i) {
#pragma unroll
        for (int u = 0; u < 8; ++u) As[(n0 + i) * 132 + j0 + u] = acc[i][u];
        int gn = row0 + n0 + i;
        if (gn < N_) {
            float4 v0 = make_float4(acc[i][0], acc[i][1], acc[i][2], acc[i][3]);
            float4 v1 = make_float4(acc[i][4], acc[i][5], acc[i][6], acc[i][7]);
            *(float4*)(g_xp + (size_t)gn * 128 + j0)     = v0;
            *(float4*)(g_xp + (size_t)gn * 128 + j0 + 4) = v1;
        }
    }
    __syncthreads();

    // a_src / a_dst row dots
    int wid = tid >> 5, lane = tid & 31;
    for (int r = wid; r < 64; r += 8) {
        float s1 = 0.f, s2 = 0.f;
        for (int k = lane; k < 128; k += 32) {
            float v = As[r * 132 + k];
            s1 += v * sAS[k];
            s2 += v * sAD[k];
        }
#pragma unroll
        for (int o = 16; o; o >>= 1) {
            s1 += __shfl_xor_sync(0xffffffffu, s1, o);
            s2 += __shfl_xor_sync(0xffffffffu, s2, o);
        }
        int gn = row0 + r;
        if (lane == 0 && gn < N_) { g_asrc[gn] = s1; g_adst[gn] = s2; }
    }
}

// ---------------- GAT aggregation: warp per destination node ----------------
__global__ __launch_bounds__(256) void k_gat(const float* __restrict__ gbias) {
    __shared__ double ssum[128], ssq[128];
    int tid = threadIdx.x;
    if (tid < 128) { ssum[tid] = 0.0; ssq[tid] = 0.0; }
    __syncthreads();

    int wid = tid >> 5, lane = tid & 31;
    int n = blockIdx.x * 8 + wid;
    if (n < N_) {
        int s0 = g_off[n], s1e = g_off[n + 1];
        float ad = g_adst[n];

        float m = -1e30f;
        for (int i = s0 + lane; i < s1e; i += 32) {
            float a = g_asrc[g_col[i]] + ad;
            a = (a > 0.f) ? a : NEG * a;
            m = fmaxf(m, a);
        }
#pragma unroll
        for (int o = 16; o; o >>= 1) m = fmaxf(m, __shfl_xor_sync(0xffffffffu, m, o));

        float se = 0.f;
        for (int i = s0 + lane; i < s1e; i += 32) {
            float a = g_asrc[g_col[i]] + ad;
            a = (a > 0.f) ? a : NEG * a;
            se += __expf(a - m);
        }
#pragma unroll
        for (int o = 16; o; o >>= 1) se += __shfl_xor_sync(0xffffffffu, se, o);
        float inv = 1.f / (se + 1e-16f);

        // software-pipelined weighted gather: prefetch next col/alpha while
        // consuming the current edge's feature vector (MLP >= 2 on L2 path)
        float4 acc = make_float4(0.f, 0.f, 0.f, 0.f);
        int cur_s = g_col[s0];
        float cur_as = g_asrc[cur_s];
        for (int i = s0; i < s1e; ++i) {
            int nxt_s = 0; float nxt_as = 0.f;
            if (i + 1 < s1e) { nxt_s = g_col[i + 1]; nxt_as = g_asrc[nxt_s]; }
            float a = cur_as + ad;
            a = (a > 0.f) ? a : NEG * a;
            float c = __expf(a - m) * inv;
            float4 v = *(const float4*)(g_xp + (size_t)cur_s * 128 + lane * 4);
            acc.x = fmaf(c, v.x, acc.x);
            acc.y = fmaf(c, v.y, acc.y);
            acc.z = fmaf(c, v.z, acc.z);
            acc.w = fmaf(c, v.w, acc.w);
            cur_s = nxt_s; cur_as = nxt_as;
        }
        float4 b = *(const float4*)(gbias + lane * 4);
        acc.x += b.x; acc.y += b.y; acc.z += b.z; acc.w += b.w;
        *(float4*)(g_out + (size_t)n * 128 + lane * 4) = acc;

        int f = lane * 4;
        atomicAdd(&ssum[f + 0], (double)acc.x);
        atomicAdd(&ssum[f + 1], (double)acc.y);
        atomicAdd(&ssum[f + 2], (double)acc.z);
        atomicAdd(&ssum[f + 3], (double)acc.w);
        atomicAdd(&ssq[f + 0], (double)acc.x * (double)acc.x);
        atomicAdd(&ssq[f + 1], (double)acc.y * (double)acc.y);
        atomicAdd(&ssq[f + 2], (double)acc.z * (double)acc.z);
        atomicAdd(&ssq[f + 3], (double)acc.w * (double)acc.w);
    }
    __syncthreads();
    if (tid < 128) {
        atomicAdd(&g_colsum[tid], ssum[tid]);
        atomicAdd(&g_colsq[tid], ssq[tid]);
    }
}

// ---------------- GraphNorm stats ----------------
__global__ void k_stats(const float* __restrict__ gnw, const float* __restrict__ gnb,
                        const float* __restrict__ gnms) {
    int f = threadIdx.x;
    if (f < 128) {
        double m = g_colsum[f] / (double)N_;
        double q = g_colsq[f] / (double)N_;
        double s = (double)gnms[f];
        double var = q - 2.0 * s * m * m + s * s * m * m;
        float inv = (float)(1.0 / sqrt(var + (double)EPSN));
        float sc = gnw[f] * inv;
        g_nscale[f] = sc;
        g_nshift[f] = gnb[f] - (float)(s * m) * sc;
    }
}

// ---------------- final: xc = [norm(out), x_]; y = mix(xc*Wc1^T+b1, xc*Wc0^T+b0) ----------------
#define SMEM_FINAL ((64 * 260 + 256 * 68 + 64 + 128 + 128) * 4)

__device__ __forceinline__ void gemm256(const float* __restrict__ A, const float* __restrict__ Wt,
                                        float acc[4][4], int n0, int jj0) {
#pragma unroll 4
    for (int k = 0; k < 256; ++k) {
        float4 w = *(const float4*)(Wt + k * 68 + jj0);
        float a[4];
#pragma unroll
        for (int i = 0; i < 4; ++i) a[i] = A[(n0 + i) * 260 + k];
#pragma unroll
        for (int i = 0; i < 4; ++i) {
            acc[i][0] = fmaf(a[i], w.x, acc[i][0]);
            acc[i][1] = fmaf(a[i], w.y, acc[i][1]);
            acc[i][2] = fmaf(a[i], w.z, acc[i][2]);
            acc[i][3] = fmaf(a[i], w.w, acc[i][3]);
        }
    }
}

__global__ __launch_bounds__(256, 1) void k_final(
    const float* __restrict__ x,
    const float* __restrict__ Wc0, const float* __restrict__ bc0,
    const float* __restrict__ Wc1, const float* __restrict__ bc1,
    const void* __restrict__ mask,
    float* __restrict__ out)
{
    extern __shared__ float sm[];
    float* Xc  = sm;
    float* Wt  = Xc + 64 * 260;
    float* cz  = Wt + 256 * 68;
    float* nsc = cz + 64;
    float* nsh = nsc + 128;

    int tid = threadIdx.x;
    int row0 = blockIdx.x * 64;

    if (tid < 128) { nsc[tid] = g_nscale[tid]; nsh[tid] = g_nshift[tid]; }
    if (tid < 64) {
        int gn = row0 + tid;
        cz[tid] = (gn < N_ && ld_mask(mask, gn)) ? ZMIX : (1.f - ZMIX);
    }
    __syncthreads();
    for (int i = tid; i < 64 * 128; i += 256) {
        int n = i >> 7, k = i & 127;
        int gn = row0 + n;
        float a = 0.f, b = 0.f;
        if (gn < N_) {
            a = g_out[(size_t)gn * 128 + k] * nsc[k] + nsh[k];
            b = x[(size_t)gn * 128 + k];
        }
        Xc[n * 260 + k] = a;
        Xc[n * 260 + 128 + k] = b;
    }

    int ty = tid >> 4, tx = tid & 15;
    int n0 = ty * 4, jj0 = tx * 4;

    for (int jc = 0; jc < 2; ++jc) {
        int jb = jc * 64;
        __syncthreads();
        for (int i = tid; i < 64 * 256; i += 256) {
            int j = i >> 8, k = i & 255;
            Wt[k * 68 + j] = Wc1[(size_t)(jb + j) * 256 + k];
        }
        __syncthreads();
        float acc1[4][4];
        {
            float bb[4];
#pragma unroll
            for (int u = 0; u < 4; ++u) bb[u] = bc1[jb + jj0 + u];
#pragma unroll
            for (int i = 0; i < 4; ++i)
#pragma unroll
                for (int u = 0; u < 4; ++u) acc1[i][u] = bb[u];
        }
        gemm256(Xc, Wt, acc1, n0, jj0);

        __syncthreads();
        for (int i = tid; i < 64 * 256; i += 256) {
            int j = i >> 8, k = i & 255;
            Wt[k * 68 + j] = Wc0[(size_t)(jb + j) * 256 + k];
        }
        __syncthreads();
        float acc0[4][4];
        {
            float bb[4];
#pragma unroll
            for (int u = 0; u < 4; ++u) bb[u] = bc0[jb + jj0 + u];
#pragma unroll
            for (int i = 0; i < 4; ++i)
#pragma unroll
                for (int u = 0; u < 4; ++u) acc0[i][u] = bb[u];
        }
        gemm256(Xc, Wt, acc0, n0, jj0);

#pragma unroll
        for (int i = 0; i < 4; ++i) {
            int gn = row0 + n0 + i;
            if (gn < N_) {
                float c1 = cz[n0 + i];
                float c0 = 1.f - c1;
                float4 r;
                r.x = c1 * acc1[i][0] + c0 * acc0[i][0];
                r.y = c1 * acc1[i][1] + c0 * acc0[i][1];
                r.z = c1 * acc1[i][2] + c0 * acc0[i][2];
                r.w = c1 * acc1[i][3] + c0 * acc0[i][3];
                *(float4*)(out + (size_t)gn * 128 + jb + jj0) = r;
            }
        }
    }
}

// ---------------- launch ----------------
extern "C" void kernel_launch(void* const* d_in, const int* in_sizes, int n_in,
                              void* d_out, int out_size) {
    const float* x    = (const float*)d_in[0];
    const float* Wt0  = (const float*)d_in[2];
    const float* bt0  = (const float*)d_in[3];
    const float* Wt1  = (const float*)d_in[4];
    const float* bt1  = (const float*)d_in[5];
    const float* gW   = (const float*)d_in[6];
    const float* atts = (const float*)d_in[7];
    const float* attd = (const float*)d_in[8];
    const float* gbias= (const float*)d_in[9];
    const float* gnw  = (const float*)d_in[10];
    const float* gnb  = (const float*)d_in[11];
    const float* gnms = (const float*)d_in[12];
    const float* Wc0  = (const float*)d_in[13];
    const float* bc0  = (const float*)d_in[14];
    const float* Wc1  = (const float*)d_in[15];
    const float* bc1  = (const float*)d_in[16];
    const void*  ei   = d_in[17];
    const void*  mask = d_in[18];
    float* out = (float*)d_out;

    cudaFuncSetAttribute(k_node,  cudaFuncAttributeMaxDynamicSharedMemorySize, SMEM_NODE);
    cudaFuncSetAttribute(k_final, cudaFuncAttributeMaxDynamicSharedMemorySize, SMEM_FINAL);

    const int NB_SCAN = (N_ + 1023) / 1024;   // 98

    k_detect   <<<1, 32>>>(ei, mask);
    k_zero     <<<(N_ + 255) / 256, 256>>>();
    k_hist     <<<(E_ + 255) / 256, 256>>>(ei);
    k_scan1    <<<NB_SCAN, 1024>>>();
    k_scan2    <<<1, 32>>>(NB_SCAN);
    k_scan3    <<<NB_SCAN, 1024>>>();
    k_fillself <<<(N_ + 255) / 256, 256>>>();
    k_filledges<<<(E_ + 255) / 256, 256>>>(ei);
    k_node     <<<(N_ + 63) / 64, 256, SMEM_NODE>>>(x, Wt0, bt0, Wt1, bt1, gW, atts, attd, mask);
    k_gat      <<<(N_ + 7) / 8, 256>>>(gbias);
    k_stats    <<<1, 128>>>(gnw, gnb, gnms);
    k_final    <<<(N_ + 63) / 64, 256, SMEM_FINAL>>>(x, Wc0, bc0, Wc1, bc1, mask, out);
}

// round 6
// speedup vs baseline: 1.5450x; 1.5450x over previous
#include <cuda_runtime.h>
#include <cuda_bf16.h>
#include <math.h>

#define N_    100000
#define E_    1600000
#define ZMIX  0.8f
#define NEG   0.2f
#define EPSN  1e-5

// ---------------- device scratch (static globals; no allocation) ----------------
__device__ float  g_xp [(size_t)N_ * 128];
__device__ float  g_out[(size_t)N_ * 128];
__device__ float  g_asrc[N_];
__device__ float  g_adst[N_];
__device__ int    g_deg[N_];
__device__ int    g_off[N_ + 1];
__device__ int    g_cursor[N_];
__device__ int    g_col[E_ + N_];
__device__ int    g_bsum[128];
__device__ double g_colsum[128];
__device__ double g_colsq[128];
__device__ float  g_nscale[128];
__device__ float  g_nshift[128];
__device__ int    g_ei64;
__device__ int    g_mask4;

// ---------------- dtype detection ----------------
__global__ void k_detect(const void* ei, const void* mask) {
    int lane = threadIdx.x;
    const int* w = (const int*)ei;
    int nz = 0;
    for (int k = lane; k < 512; k += 32) nz |= (w[2 * k + 1] != 0);
    const unsigned char* mb = (const unsigned char*)mask;
    int mnz = 0;
    for (int k = lane; k < 500; k += 32) {
        int o = k * 196 + (k % 3) + 1;
        mnz |= (mb[o] != 0);
    }
    nz  = __any_sync(0xffffffffu, nz);
    mnz = __any_sync(0xffffffffu, mnz);
    if (lane == 0) { g_ei64 = !nz; g_mask4 = !mnz; }
}

__device__ __forceinline__ int ld_ei(const void* ei, size_t idx) {
    long long v = g_ei64 ? ((const long long*)ei)[idx]
                         : (long long)((const int*)ei)[idx];
    int t = (int)v;
    if (t < 0) t = 0;
    if (t >= N_) t = N_ - 1;
    return t;
}

__device__ __forceinline__ int ld_mask(const void* m, int i) {
    return g_mask4 ? (((const int*)m)[i] != 0) : (((const unsigned char*)m)[i] != 0);
}

// ---------------- CSR build ----------------
__global__ void k_zero() {
    int i = blockIdx.x * blockDim.x + threadIdx.x;
    if (i < N_) g_deg[i] = 1;
    if (i < 128) { g_colsum[i] = 0.0; g_colsq[i] = 0.0; }
}

__global__ void k_hist(const void* __restrict__ ei) {
    int e = blockIdx.x * blockDim.x + threadIdx.x;
    if (e < E_) atomicAdd(&g_deg[ld_ei(ei, (size_t)E_ + e)], 1);
}

__global__ void k_scan1() {
    __shared__ int s[1024];
    int tid = threadIdx.x;
    int g = blockIdx.x * 1024 + tid;
    int v = (g < N_) ? g_deg[g] : 0;
    s[tid] = v;
    __syncthreads();
    for (int o = 1; o < 1024; o <<= 1) {
        int t = (tid >= o) ? s[tid - o] : 0;
        __syncthreads();
        s[tid] += t;
        __syncthreads();
    }
    if (g < N_) g_off[g] = s[tid] - v;
    if (tid == 1023) g_bsum[blockIdx.x] = s[1023];
}

__global__ void k_scan2(int nb) {
    if (threadIdx.x == 0) {
        int r = 0;
        for (int b = 0; b < nb; b++) { int t = g_bsum[b]; g_bsum[b] = r; r += t; }
    }
}

__global__ void k_scan3() {
    int tid = threadIdx.x;
    int g = blockIdx.x * 1024 + tid;
    if (g < N_) g_off[g] += g_bsum[blockIdx.x];
    if (g == 0) g_off[N_] = N_ + E_;
}

__global__ void k_fillself() {
    int i = blockIdx.x * blockDim.x + threadIdx.x;
    if (i < N_) { int o = g_off[i]; g_col[o] = i; g_cursor[i] = o + 1; }
}

__global__ void k_filledges(const void* __restrict__ ei) {
    int e = blockIdx.x * blockDim.x + threadIdx.x;
    if (e < E_) {
        int d = ld_ei(ei, (size_t)E_ + e);
        int p = atomicAdd(&g_cursor[d], 1);
        g_col[p] = ld_ei(ei, e);
    }
}

// ---------------- bf16x3 mma building blocks ----------------
__device__ __forceinline__ unsigned pack2(float x0, float x1) {
    __nv_bfloat162 v = __floats2bfloat162_rn(x0, x1);
    return *reinterpret_cast<unsigned*>(&v);
}

__device__ __forceinline__ void split2(float x0, float x1, unsigned &h, unsigned &l) {
    float h0 = __bfloat162float(__float2bfloat16(x0));
    float h1 = __bfloat162float(__float2bfloat16(x1));
    h = pack2(x0, x1);
    l = pack2(x0 - h0, x1 - h1);
}

__device__ __forceinline__ void mma4(float* c,
    unsigned a0, unsigned a1, unsigned a2, unsigned a3, unsigned b0, unsigned b1) {
    asm volatile(
        "mma.sync.aligned.m16n8k16.row.col.f32.bf16.bf16.f32 "
        "{%0,%1,%2,%3}, {%4,%5,%6,%7}, {%8,%9}, {%0,%1,%2,%3};\n"
        : "+f"(c[0]), "+f"(c[1]), "+f"(c[2]), "+f"(c[3])
        : "r"(a0), "r"(a1), "r"(a2), "r"(a3), "r"(b0), "r"(b1));
}

// warp-tile GEMM: KS k16-steps, NT 8-col ntiles, W = u32 row width of operand tiles.
template<int KS, int NT, int W>
__device__ __forceinline__ void wgemm(const unsigned* __restrict__ Ah, const unsigned* __restrict__ Al,
                                      const unsigned* __restrict__ Bh, const unsigned* __restrict__ Bl,
                                      float (*acc)[4], int ra, int rb, int jbg, int q) {
    for (int ks = 0; ks < KS; ++ks) {
        int o = ks * 8;
        unsigned ah0 = Ah[ra + o], ah1 = Ah[rb + o], ah2 = Ah[ra + o + 4], ah3 = Ah[rb + o + 4];
        unsigned al0 = Al[ra + o], al1 = Al[rb + o], al2 = Al[ra + o + 4], al3 = Al[rb + o + 4];
#pragma unroll
        for (int j = 0; j < NT; ++j) {
            int bo = (jbg + 8 * j) * W + q + o;
            unsigned bh0 = Bh[bo], bh1 = Bh[bo + 4];
            unsigned bl0 = Bl[bo], bl1 = Bl[bo + 4];
            mma4(acc[j], ah0, ah1, ah2, ah3, bh0, bh1);
            mma4(acc[j], ah0, ah1, ah2, ah3, bl0, bl1);
            mma4(acc[j], al0, al1, al2, al3, bh0, bh1);
        }
    }
}

// ---------------- fused node kernel (tensor-core) ----------------
#define SMEM_NODE ((64*66*2 + 128*66*2) * 4 + (128*2 + 64*3) * 4)

__global__ __launch_bounds__(256, 1) void k_node(
    const float* __restrict__ x,
    const float* __restrict__ Wt0g, const float* __restrict__ bt0,
    const float* __restrict__ Wt1g, const float* __restrict__ bt1,
    const float* __restrict__ gWg,
    const float* __restrict__ atts, const float* __restrict__ attd,
    const void* __restrict__ mask)
{
    extern __shared__ unsigned smu[];
    unsigned* Ah = smu;
    unsigned* Al = Ah + 64 * 66;
    unsigned* Wh = Al + 64 * 66;
    unsigned* Wl = Wh + 128 * 66;
    float* sAS = (float*)(Wl + 128 * 66);
    float* sAD = sAS + 128;
    float* sS  = sAD + 128;
    float* sD  = sS + 64;
    float* cz  = sD + 64;

    int tid = threadIdx.x;
    int row0 = blockIdx.x * 64;

    for (int p = tid; p < 64 * 64; p += 256) {
        int n = p >> 6, kp = p & 63;
        int gn = row0 + n;
        float2 v = make_float2(0.f, 0.f);
        if (gn < N_) v = *(const float2*)(x + (size_t)gn * 128 + 2 * kp);
        unsigned h, l; split2(v.x, v.y, h, l);
        Ah[n * 66 + kp] = h; Al[n * 66 + kp] = l;
    }
    if (tid < 128) { sAS[tid] = atts[tid]; sAD[tid] = attd[tid]; }
    if (tid < 64) {
        sS[tid] = 0.f; sD[tid] = 0.f;
        int gn = row0 + tid;
        cz[tid] = (gn < N_ && ld_mask(mask, gn)) ? ZMIX : (1.f - ZMIX);
    }
    for (int p = tid; p < 128 * 64; p += 256) {
        int j = p >> 6, kp = p & 63;
        float2 v = *(const float2*)(Wt1g + (size_t)j * 128 + 2 * kp);
        unsigned h, l; split2(v.x, v.y, h, l);
        Wh[j * 66 + kp] = h; Wl[j * 66 + kp] = l;
    }
    __syncthreads();

    int lane = tid & 31, w = tid >> 5;
    int g = lane >> 2, q = lane & 3;
    int m16 = (w >> 1) * 16;
    int jb  = (w & 1) * 64;
    int ra = (m16 + g) * 66 + q;
    int rb = (m16 + g + 8) * 66 + q;
    int jbg = jb + g;

    // phase A: h1 = x W1^T + b1
    float accA[8][4];
#pragma unroll
    for (int j = 0; j < 8; ++j) {
        float2 bv = *(const float2*)(bt1 + jb + 8 * j + 2 * q);
        accA[j][0] = bv.x; accA[j][1] = bv.y; accA[j][2] = bv.x; accA[j][3] = bv.y;
    }
    wgemm<8, 8, 66>(Ah, Al, Wh, Wl, accA, ra, rb, jbg, q);

    // phase B: load W_t0, h0 = x W0^T + b0
    __syncthreads();
    for (int p = tid; p < 128 * 64; p += 256) {
        int j = p >> 6, kp = p & 63;
        float2 v = *(const float2*)(Wt0g + (size_t)j * 128 + 2 * kp);
        unsigned h, l; split2(v.x, v.y, h, l);
        Wh[j * 66 + kp] = h; Wl[j * 66 + kp] = l;
    }
    __syncthreads();
    float accB[8][4];
#pragma unroll
    for (int j = 0; j < 8; ++j) {
        float2 bv = *(const float2*)(bt0 + jb + 8 * j + 2 * q);
        accB[j][0] = bv.x; accB[j][1] = bv.y; accB[j][2] = bv.x; accB[j][3] = bv.y;
    }
    wgemm<8, 8, 66>(Ah, Al, Wh, Wl, accB, ra, rb, jbg, q);
    __syncthreads();

    // mix -> Xb, store bf16 hi/lo into Ah/Al
    {
        float c0 = cz[m16 + g], c1 = cz[m16 + g + 8];
#pragma unroll
        for (int j = 0; j < 8; ++j) {
            int colp = (jb >> 1) + 4 * j + q;
            float xb0 = c0 * fmaxf(accA[j][0], 0.f) + (1.f - c0) * fmaxf(accB[j][0], 0.f);
            float xb1 = c0 * fmaxf(accA[j][1], 0.f) + (1.f - c0) * fmaxf(accB[j][1], 0.f);
            float xb2 = c1 * fmaxf(accA[j][2], 0.f) + (1.f - c1) * fmaxf(accB[j][2], 0.f);
            float xb3 = c1 * fmaxf(accA[j][3], 0.f) + (1.f - c1) * fmaxf(accB[j][3], 0.f);
            unsigned h, l;
            split2(xb0, xb1, h, l);
            Ah[(m16 + g) * 66 + colp] = h; Al[(m16 + g) * 66 + colp] = l;
            split2(xb2, xb3, h, l);
            Ah[(m16 + g + 8) * 66 + colp] = h; Al[(m16 + g + 8) * 66 + colp] = l;
        }
    }
    __syncthreads();
    // phase C: load gat_W, xp = Xb gW^T
    for (int p = tid; p < 128 * 64; p += 256) {
        int j = p >> 6, kp = p & 63;
        float2 v = *(const float2*)(gWg + (size_t)j * 128 + 2 * kp);
        unsigned h, l; split2(v.x, v.y, h, l);
        Wh[j * 66 + kp] = h; Wl[j * 66 + kp] = l;
    }
    __syncthreads();
    float accC[8][4];
#pragma unroll
    for (int j = 0; j < 8; ++j) { accC[j][0] = accC[j][1] = accC[j][2] = accC[j][3] = 0.f; }
    wgemm<8, 8, 66>(Ah, Al, Wh, Wl, accC, ra, rb, jbg, q);

    // epilogue: store xp + att dots
    {
        int gn0 = row0 + m16 + g, gn1 = gn0 + 8;
        float s1r0 = 0.f, s2r0 = 0.f, s1r1 = 0.f, s2r1 = 0.f;
#pragma unroll
        for (int j = 0; j < 8; ++j) {
            int col = jb + 8 * j + 2 * q;
            if (gn0 < N_) *(float2*)(g_xp + (size_t)gn0 * 128 + col) = make_float2(accC[j][0], accC[j][1]);
            if (gn1 < N_) *(float2*)(g_xp + (size_t)gn1 * 128 + col) = make_float2(accC[j][2], accC[j][3]);
            float as0 = sAS[col], as1 = sAS[col + 1];
            float ad0 = sAD[col], ad1 = sAD[col + 1];
            s1r0 += accC[j][0] * as0 + accC[j][1] * as1;
            s2r0 += accC[j][0] * ad0 + accC[j][1] * ad1;
            s1r1 += accC[j][2] * as0 + accC[j][3] * as1;
            s2r1 += accC[j][2] * ad0 + accC[j][3] * ad1;
        }
        s1r0 += __shfl_xor_sync(0xffffffffu, s1r0, 1); s1r0 += __shfl_xor_sync(0xffffffffu, s1r0, 2);
        s2r0 += __shfl_xor_sync(0xffffffffu, s2r0, 1); s2r0 += __shfl_xor_sync(0xffffffffu, s2r0, 2);
        s1r1 += __shfl_xor_sync(0xffffffffu, s1r1, 1); s1r1 += __shfl_xor_sync(0xffffffffu, s1r1, 2);
        s2r1 += __shfl_xor_sync(0xffffffffu, s2r1, 1); s2r1 += __shfl_xor_sync(0xffffffffu, s2r1, 2);
        if (q == 0) {
            atomicAdd(&sS[m16 + g], s1r0);     atomicAdd(&sD[m16 + g], s2r0);
            atomicAdd(&sS[m16 + g + 8], s1r1); atomicAdd(&sD[m16 + g + 8], s2r1);
        }
    }
    __syncthreads();
    if (tid < 64) {
        int gn = row0 + tid;
        if (gn < N_) { g_asrc[gn] = sS[tid]; g_adst[gn] = sD[tid]; }
    }
}

// ---------------- GAT aggregation ----------------
__global__ __launch_bounds__(256) void k_gat(const float* __restrict__ gbias) {
    __shared__ double ssum[128], ssq[128];
    int tid = threadIdx.x;
    if (tid < 128) { ssum[tid] = 0.0; ssq[tid] = 0.0; }
    __syncthreads();

    int wid = tid >> 5, lane = tid & 31;
    int n = blockIdx.x * 8 + wid;
    if (n < N_) {
        int s0 = g_off[n], s1e = g_off[n + 1];
        float ad = g_adst[n];

        float m = -1e30f;
        for (int i = s0 + lane; i < s1e; i += 32) {
            float a = g_asrc[g_col[i]] + ad;
            a = (a > 0.f) ? a : NEG * a;
            m = fmaxf(m, a);
        }
#pragma unroll
        for (int o = 16; o; o >>= 1) m = fmaxf(m, __shfl_xor_sync(0xffffffffu, m, o));

        float se = 0.f;
        for (int i = s0 + lane; i < s1e; i += 32) {
            float a = g_asrc[g_col[i]] + ad;
            a = (a > 0.f) ? a : NEG * a;
            se += __expf(a - m);
        }
#pragma unroll
        for (int o = 16; o; o >>= 1) se += __shfl_xor_sync(0xffffffffu, se, o);
        float inv = 1.f / (se + 1e-16f);

        float4 acc = make_float4(0.f, 0.f, 0.f, 0.f);
        int cur_s = g_col[s0];
        float cur_as = g_asrc[cur_s];
        for (int i = s0; i < s1e; ++i) {
            int nxt_s = 0; float nxt_as = 0.f;
            if (i + 1 < s1e) { nxt_s = g_col[i + 1]; nxt_as = g_asrc[nxt_s]; }
            float a = cur_as + ad;
            a = (a > 0.f) ? a : NEG * a;
            float c = __expf(a - m) * inv;
            float4 v = *(const float4*)(g_xp + (size_t)cur_s * 128 + lane * 4);
            acc.x = fmaf(c, v.x, acc.x);
            acc.y = fmaf(c, v.y, acc.y);
            acc.z = fmaf(c, v.z, acc.z);
            acc.w = fmaf(c, v.w, acc.w);
            cur_s = nxt_s; cur_as = nxt_as;
        }
        float4 b = *(const float4*)(gbias + lane * 4);
        acc.x += b.x; acc.y += b.y; acc.z += b.z; acc.w += b.w;
        *(float4*)(g_out + (size_t)n * 128 + lane * 4) = acc;

        int f = lane * 4;
        atomicAdd(&ssum[f + 0], (double)acc.x);
        atomicAdd(&ssum[f + 1], (double)acc.y);
        atomicAdd(&ssum[f + 2], (double)acc.z);
        atomicAdd(&ssum[f + 3], (double)acc.w);
        atomicAdd(&ssq[f + 0], (double)acc.x * (double)acc.x);
        atomicAdd(&ssq[f + 1], (double)acc.y * (double)acc.y);
        atomicAdd(&ssq[f + 2], (double)acc.z * (double)acc.z);
        atomicAdd(&ssq[f + 3], (double)acc.w * (double)acc.w);
    }
    __syncthreads();
    if (tid < 128) {
        atomicAdd(&g_colsum[tid], ssum[tid]);
        atomicAdd(&g_colsq[tid], ssq[tid]);
    }
}

// ---------------- GraphNorm stats ----------------
__global__ void k_stats(const float* __restrict__ gnw, const float* __restrict__ gnb,
                        const float* __restrict__ gnms) {
    int f = threadIdx.x;
    if (f < 128) {
        double m = g_colsum[f] / (double)N_;
        double q = g_colsq[f] / (double)N_;
        double s = (double)gnms[f];
        double var = q - 2.0 * s * m * m + s * s * m * m;
        float inv = (float)(1.0 / sqrt(var + (double)EPSN));
        float sc = gnw[f] * inv;
        g_nscale[f] = sc;
        g_nshift[f] = gnb[f] - (float)(s * m) * sc;
    }
}

// ---------------- final kernel (tensor-core) ----------------
#define SMEM_FINAL ((64*130*4) * 4 + (128*2 + 64) * 4)

__global__ __launch_bounds__(256, 1) void k_final(
    const float* __restrict__ x,
    const float* __restrict__ Wc0, const float* __restrict__ bc0,
    const float* __restrict__ Wc1, const float* __restrict__ bc1,
    const void* __restrict__ mask,
    float* __restrict__ out)
{
    extern __shared__ unsigned smu[];
    unsigned* XCh = smu;
    unsigned* XCl = XCh + 64 * 130;
    unsigned* Wh  = XCl + 64 * 130;
    unsigned* Wl  = Wh + 64 * 130;
    float* nsc = (float*)(Wl + 64 * 130);
    float* nsh = nsc + 128;
    float* cz  = nsh + 128;

    int tid = threadIdx.x;
    int row0 = blockIdx.x * 64;

    if (tid < 128) { nsc[tid] = g_nscale[tid]; nsh[tid] = g_nshift[tid]; }
    if (tid < 64) {
        int gn = row0 + tid;
        cz[tid] = (gn < N_ && ld_mask(mask, gn)) ? ZMIX : (1.f - ZMIX);
    }
    __syncthreads();

    for (int p = tid; p < 64 * 128; p += 256) {
        int n = p >> 7, kp = p & 127;
        int col = 2 * kp;
        int gn = row0 + n;
        float v0 = 0.f, v1 = 0.f;
        if (gn < N_) {
            if (col < 128) {
                float2 t = *(const float2*)(g_out + (size_t)gn * 128 + col);
                v0 = t.x * nsc[col] + nsh[col];
                v1 = t.y * nsc[col + 1] + nsh[col + 1];
            } else {
                float2 t = *(const float2*)(x + (size_t)gn * 128 + col - 128);
                v0 = t.x; v1 = t.y;
            }
        }
        unsigned h, l; split2(v0, v1, h, l);
        XCh[n * 130 + kp] = h; XCl[n * 130 + kp] = l;
    }

    int lane = tid & 31, w = tid >> 5;
    int g = lane >> 2, q = lane & 3;
    int m16 = (w >> 1) * 16;
    int nb  = (w & 1) * 32;
    int ra = (m16 + g) * 130 + q;
    int rb = (m16 + g + 8) * 130 + q;
    int jbg = nb + g;

    for (int jc = 0; jc < 2; ++jc) {
        int jbase = jc * 64;
        __syncthreads();
        for (int p = tid; p < 64 * 128; p += 256) {
            int j = p >> 7, kp = p & 127;
            float2 v = *(const float2*)(Wc1 + (size_t)(jbase + j) * 256 + 2 * kp);
            unsigned h, l; split2(v.x, v.y, h, l);
            Wh[j * 130 + kp] = h; Wl[j * 130 + kp] = l;
        }
        __syncthreads();
        float acc1[4][4];
#pragma unroll
        for (int j = 0; j < 4; ++j) {
            float2 bv = *(const float2*)(bc1 + jbase + nb + 8 * j + 2 * q);
            acc1[j][0] = bv.x; acc1[j][1] = bv.y; acc1[j][2] = bv.x; acc1[j][3] = bv.y;
        }
        wgemm<16, 4, 130>(XCh, XCl, Wh, Wl, acc1, ra, rb, jbg, q);

        __syncthreads();
        for (int p = tid; p < 64 * 128; p += 256) {
            int j = p >> 7, kp = p & 127;
            float2 v = *(const float2*)(Wc0 + (size_t)(jbase + j) * 256 + 2 * kp);
            unsigned h, l; split2(v.x, v.y, h, l);
            Wh[j * 130 + kp] = h; Wl[j * 130 + kp] = l;
        }
        __syncthreads();
        float acc0[4][4];
#pragma unroll
        for (int j = 0; j < 4; ++j) {
            float2 bv = *(const float2*)(bc0 + jbase + nb + 8 * j + 2 * q);
            acc0[j][0] = bv.x; acc0[j][1] = bv.y; acc0[j][2] = bv.x; acc0[j][3] = bv.y;
        }
        wgemm<16, 4, 130>(XCh, XCl, Wh, Wl, acc0, ra, rb, jbg, q);

        {
            float c0 = cz[m16 + g], c1 = cz[m16 + g + 8];
            int gn0 = row0 + m16 + g, gn1 = gn0 + 8;
#pragma unroll
            for (int j = 0; j < 4; ++j) {
                int col = jbase + nb + 8 * j + 2 * q;
                if (gn0 < N_) {
                    float2 r;
                    r.x = c0 * acc1[j][0] + (1.f - c0) * acc0[j][0];
                    r.y = c0 * acc1[j][1] + (1.f - c0) * acc0[j][1];
                    *(float2*)(out + (size_t)gn0 * 128 + col) = r;
                }
                if (gn1 < N_) {
                    float2 r;
                    r.x = c1 * acc1[j][2] + (1.f - c1) * acc0[j][2];
                    r.y = c1 * acc1[j][3] + (1.f - c1) * acc0[j][3];
                    *(float2*)(out + (size_t)gn1 * 128 + col) = r;
                }
            }
        }
    }
}

// ---------------- launch ----------------
extern "C" void kernel_launch(void* const* d_in, const int* in_sizes, int n_in,
                              void* d_out, int out_size) {
    const float* x    = (const float*)d_in[0];
    const float* Wt0  = (const float*)d_in[2];
    const float* bt0  = (const float*)d_in[3];
    const float* Wt1  = (const float*)d_in[4];
    const float* bt1  = (const float*)d_in[5];
    const float* gW   = (const float*)d_in[6];
    const float* atts = (const float*)d_in[7];
    const float* attd = (const float*)d_in[8];
    const float* gbias= (const float*)d_in[9];
    const float* gnw  = (const float*)d_in[10];
    const float* gnb  = (const float*)d_in[11];
    const float* gnms = (const float*)d_in[12];
    const float* Wc0  = (const float*)d_in[13];
    const float* bc0  = (const float*)d_in[14];
    const float* Wc1  = (const float*)d_in[15];
    const float* bc1  = (const float*)d_in[16];
    const void*  ei   = d_in[17];
    const void*  mask = d_in[18];
    float* out = (float*)d_out;

    cudaFuncSetAttribute(k_node,  cudaFuncAttributeMaxDynamicSharedMemorySize, SMEM_NODE);
    cudaFuncSetAttribute(k_final, cudaFuncAttributeMaxDynamicSharedMemorySize, SMEM_FINAL);

    const int NB_SCAN = (N_ + 1023) / 1024;

    k_detect   <<<1, 32>>>(ei, mask);
    k_zero     <<<(N_ + 255) / 256, 256>>>();
    k_hist     <<<(E_ + 255) / 256, 256>>>(ei);
    k_scan1    <<<NB_SCAN, 1024>>>();
    k_scan2    <<<1, 32>>>(NB_SCAN);
    k_scan3    <<<NB_SCAN, 1024>>>();
    k_fillself <<<(N_ + 255) / 256, 256>>>();
    k_filledges<<<(E_ + 255) / 256, 256>>>(ei);
    k_node     <<<(N_ + 63) / 64, 256, SMEM_NODE>>>(x, Wt0, bt0, Wt1, bt1, gW, atts, attd, mask);
    k_gat      <<<(N_ + 7) / 8, 256>>>(gbias);
    k_stats    <<<1, 128>>>(gnw, gnb, gnms);
    k_final    <<<(N_ + 63) / 64, 256, SMEM_FINAL>>>(x, Wc0, bc0, Wc1, bc1, mask, out);
}

// round 8
// speedup vs baseline: 1.5651x; 1.0130x over previous
#include <cuda_runtime.h>
#include <cuda_bf16.h>
#include <math.h>

#define N_    100000
#define E_    1600000
#define ZMIX  0.8f
#define NEG   0.2f
#define EPSN  1e-5

// ---------------- device scratch (static globals; no allocation) ----------------
__device__ float  g_xp [(size_t)N_ * 128];
__device__ float  g_out[(size_t)N_ * 128];
__device__ float  g_asrc[N_];
__device__ float  g_adst[N_];
__device__ int    g_deg[N_];
__device__ int    g_off[N_ + 1];
__device__ int    g_cursor[N_];
__device__ int    g_col[E_ + N_];
__device__ int    g_bsum[128];
__device__ double g_colsum[128];
__device__ double g_colsq[128];
__device__ float  g_nscale[128];
__device__ float  g_nshift[128];
__device__ int    g_ei64;
__device__ int    g_mask4;

// ---------------- dtype detection ----------------
__global__ void k_detect(const void* ei, const void* mask) {
    int lane = threadIdx.x;
    const int* w = (const int*)ei;
    int nz = 0;
    for (int k = lane; k < 512; k += 32) nz |= (w[2 * k + 1] != 0);
    const unsigned char* mb = (const unsigned char*)mask;
    int mnz = 0;
    for (int k = lane; k < 500; k += 32) {
        int o = k * 196 + (k % 3) + 1;
        mnz |= (mb[o] != 0);
    }
    nz  = __any_sync(0xffffffffu, nz);
    mnz = __any_sync(0xffffffffu, mnz);
    if (lane == 0) { g_ei64 = !nz; g_mask4 = !mnz; }
}

__device__ __forceinline__ int ld_ei(const void* ei, size_t idx) {
    long long v = g_ei64 ? ((const long long*)ei)[idx]
                         : (long long)((const int*)ei)[idx];
    int t = (int)v;
    if (t < 0) t = 0;
    if (t >= N_) t = N_ - 1;
    return t;
}

__device__ __forceinline__ int ld_mask(const void* m, int i) {
    return g_mask4 ? (((const int*)m)[i] != 0) : (((const unsigned char*)m)[i] != 0);
}

// ---------------- CSR build ----------------
__global__ void k_zero() {
    int i = blockIdx.x * blockDim.x + threadIdx.x;
    if (i < N_) g_deg[i] = 1;
    if (i < 128) { g_colsum[i] = 0.0; g_colsq[i] = 0.0; }
}

__global__ void k_hist(const void* __restrict__ ei) {
    int e = blockIdx.x * blockDim.x + threadIdx.x;
    if (e < E_) atomicAdd(&g_deg[ld_ei(ei, (size_t)E_ + e)], 1);
}

__global__ void k_scan1() {
    __shared__ int s[1024];
    int tid = threadIdx.x;
    int g = blockIdx.x * 1024 + tid;
    int v = (g < N_) ? g_deg[g] : 0;
    s[tid] = v;
    __syncthreads();
    for (int o = 1; o < 1024; o <<= 1) {
        int t = (tid >= o) ? s[tid - o] : 0;
        __syncthreads();
        s[tid] += t;
        __syncthreads();
    }
    if (g < N_) g_off[g] = s[tid] - v;
    if (tid == 1023) g_bsum[blockIdx.x] = s[1023];
}

__global__ void k_scan2(int nb) {
    if (threadIdx.x == 0) {
        int r = 0;
        for (int b = 0; b < nb; b++) { int t = g_bsum[b]; g_bsum[b] = r; r += t; }
    }
}

__global__ void k_scan3() {
    int tid = threadIdx.x;
    int g = blockIdx.x * 1024 + tid;
    if (g < N_) g_off[g] += g_bsum[blockIdx.x];
    if (g == 0) g_off[N_] = N_ + E_;
}

__global__ void k_fillself() {
    int i = blockIdx.x * blockDim.x + threadIdx.x;
    if (i < N_) { int o = g_off[i]; g_col[o] = i; g_cursor[i] = o + 1; }
}

__global__ void k_filledges(const void* __restrict__ ei) {
    int e = blockIdx.x * blockDim.x + threadIdx.x;
    if (e < E_) {
        int d = ld_ei(ei, (size_t)E_ + e);
        int p = atomicAdd(&g_cursor[d], 1);
        g_col[p] = ld_ei(ei, e);
    }
}

// ---------------- bf16x3 mma building blocks ----------------
__device__ __forceinline__ unsigned pack2(float x0, float x1) {
    __nv_bfloat162 v = __floats2bfloat162_rn(x0, x1);
    return *reinterpret_cast<unsigned*>(&v);
}

__device__ __forceinline__ void split2(float x0, float x1, unsigned &h, unsigned &l) {
    float h0 = __bfloat162float(__float2bfloat16(x0));
    float h1 = __bfloat162float(__float2bfloat16(x1));
    h = pack2(x0, x1);
    l = pack2(x0 - h0, x1 - h1);
}

__device__ __forceinline__ void mma4(float* c,
    unsigned a0, unsigned a1, unsigned a2, unsigned a3, unsigned b0, unsigned b1) {
    asm volatile(
        "mma.sync.aligned.m16n8k16.row.col.f32.bf16.bf16.f32 "
        "{%0,%1,%2,%3}, {%4,%5,%6,%7}, {%8,%9}, {%0,%1,%2,%3};\n"
        : "+f"(c[0]), "+f"(c[1]), "+f"(c[2]), "+f"(c[3])
        : "r"(a0), "r"(a1), "r"(a2), "r"(a3), "r"(b0), "r"(b1));
}

// warp-tile GEMM: KS k16-steps, NT 8-col ntiles, W = u32 row width of operand tiles.
template<int KS, int NT, int W>
__device__ __forceinline__ void wgemm(const unsigned* __restrict__ Ah, const unsigned* __restrict__ Al,
                                      const unsigned* __restrict__ Bh, const unsigned* __restrict__ Bl,
                                      float (*acc)[4], int ra, int rb, int jbg, int q) {
    for (int ks = 0; ks < KS; ++ks) {
        int o = ks * 8;
        unsigned ah0 = Ah[ra + o], ah1 = Ah[rb + o], ah2 = Ah[ra + o + 4], ah3 = Ah[rb + o + 4];
        unsigned al0 = Al[ra + o], al1 = Al[rb + o], al2 = Al[ra + o + 4], al3 = Al[rb + o + 4];
#pragma unroll
        for (int j = 0; j < NT; ++j) {
            int bo = (jbg + 8 * j) * W + q + o;
            unsigned bh0 = Bh[bo], bh1 = Bh[bo + 4];
            unsigned bl0 = Bl[bo], bl1 = Bl[bo + 4];
            mma4(acc[j], ah0, ah1, ah2, ah3, bh0, bh1);
            mma4(acc[j], ah0, ah1, ah2, ah3, bl0, bl1);
            mma4(acc[j], al0, al1, al2, al3, bh0, bh1);
        }
    }
}

// ---------------- fused node kernel (tensor-core) ----------------
#define SMEM_NODE ((64*66*2 + 128*66*2) * 4 + (128*2 + 64*3) * 4)

__global__ __launch_bounds__(256, 1) void k_node(
    const float* __restrict__ x,
    const float* __restrict__ Wt0g, const float* __restrict__ bt0,
    const float* __restrict__ Wt1g, const float* __restrict__ bt1,
    const float* __restrict__ gWg,
    const float* __restrict__ atts, const float* __restrict__ attd,
    const void* __restrict__ mask)
{
    extern __shared__ unsigned smu[];
    unsigned* Ah = smu;
    unsigned* Al = Ah + 64 * 66;
    unsigned* Wh = Al + 64 * 66;
    unsigned* Wl = Wh + 128 * 66;
    float* sAS = (float*)(Wl + 128 * 66);
    float* sAD = sAS + 128;
    float* sS  = sAD + 128;
    float* sD  = sS + 64;
    float* cz  = sD + 64;

    int tid = threadIdx.x;
    int row0 = blockIdx.x * 64;

    for (int p = tid; p < 64 * 64; p += 256) {
        int n = p >> 6, kp = p & 63;
        int gn = row0 + n;
        float2 v = make_float2(0.f, 0.f);
        if (gn < N_) v = *(const float2*)(x + (size_t)gn * 128 + 2 * kp);
        unsigned h, l; split2(v.x, v.y, h, l);
        Ah[n * 66 + kp] = h; Al[n * 66 + kp] = l;
    }
    if (tid < 128) { sAS[tid] = atts[tid]; sAD[tid] = attd[tid]; }
    if (tid < 64) {
        sS[tid] = 0.f; sD[tid] = 0.f;
        int gn = row0 + tid;
        cz[tid] = (gn < N_ && ld_mask(mask, gn)) ? ZMIX : (1.f - ZMIX);
    }
    for (int p = tid; p < 128 * 64; p += 256) {
        int j = p >> 6, kp = p & 63;
        float2 v = *(const float2*)(Wt1g + (size_t)j * 128 + 2 * kp);
        unsigned h, l; split2(v.x, v.y, h, l);
        Wh[j * 66 + kp] = h; Wl[j * 66 + kp] = l;
    }
    __syncthreads();

    int lane = tid & 31, w = tid >> 5;
    int g = lane >> 2, q = lane & 3;
    int m16 = (w >> 1) * 16;
    int jb  = (w & 1) * 64;
    int ra = (m16 + g) * 66 + q;
    int rb = (m16 + g + 8) * 66 + q;
    int jbg = jb + g;

    // phase A: h1 = x W1^T + b1
    float accA[8][4];
#pragma unroll
    for (int j = 0; j < 8; ++j) {
        float2 bv = *(const float2*)(bt1 + jb + 8 * j + 2 * q);
        accA[j][0] = bv.x; accA[j][1] = bv.y; accA[j][2] = bv.x; accA[j][3] = bv.y;
    }
    wgemm<8, 8, 66>(Ah, Al, Wh, Wl, accA, ra, rb, jbg, q);

    // phase B: load W_t0, h0 = x W0^T + b0
    __syncthreads();
    for (int p = tid; p < 128 * 64; p += 256) {
        int j = p >> 6, kp = p & 63;
        float2 v = *(const float2*)(Wt0g + (size_t)j * 128 + 2 * kp);
        unsigned h, l; split2(v.x, v.y, h, l);
        Wh[j * 66 + kp] = h; Wl[j * 66 + kp] = l;
    }
    __syncthreads();
    float accB[8][4];
#pragma unroll
    for (int j = 0; j < 8; ++j) {
        float2 bv = *(const float2*)(bt0 + jb + 8 * j + 2 * q);
        accB[j][0] = bv.x; accB[j][1] = bv.y; accB[j][2] = bv.x; accB[j][3] = bv.y;
    }
    wgemm<8, 8, 66>(Ah, Al, Wh, Wl, accB, ra, rb, jbg, q);
    __syncthreads();

    // mix -> Xb, store bf16 hi/lo into Ah/Al
    {
        float c0 = cz[m16 + g], c1 = cz[m16 + g + 8];
#pragma unroll
        for (int j = 0; j < 8; ++j) {
            int colp = (jb >> 1) + 4 * j + q;
            float xb0 = c0 * fmaxf(accA[j][0], 0.f) + (1.f - c0) * fmaxf(accB[j][0], 0.f);
            float xb1 = c0 * fmaxf(accA[j][1], 0.f) + (1.f - c0) * fmaxf(accB[j][1], 0.f);
            float xb2 = c1 * fmaxf(accA[j][2], 0.f) + (1.f - c1) * fmaxf(accB[j][2], 0.f);
            float xb3 = c1 * fmaxf(accA[j][3], 0.f) + (1.f - c1) * fmaxf(accB[j][3], 0.f);
            unsigned h, l;
            split2(xb0, xb1, h, l);
            Ah[(m16 + g) * 66 + colp] = h; Al[(m16 + g) * 66 + colp] = l;
            split2(xb2, xb3, h, l);
            Ah[(m16 + g + 8) * 66 + colp] = h; Al[(m16 + g + 8) * 66 + colp] = l;
        }
    }
    __syncthreads();
    // phase C: load gat_W, xp = Xb gW^T
    for (int p = tid; p < 128 * 64; p += 256) {
        int j = p >> 6, kp = p & 63;
        float2 v = *(const float2*)(gWg + (size_t)j * 128 + 2 * kp);
        unsigned h, l; split2(v.x, v.y, h, l);
        Wh[j * 66 + kp] = h; Wl[j * 66 + kp] = l;
    }
    __syncthreads();
    float accC[8][4];
#pragma unroll
    for (int j = 0; j < 8; ++j) { accC[j][0] = accC[j][1] = accC[j][2] = accC[j][3] = 0.f; }
    wgemm<8, 8, 66>(Ah, Al, Wh, Wl, accC, ra, rb, jbg, q);

    // epilogue: store xp + att dots
    {
        int gn0 = row0 + m16 + g, gn1 = gn0 + 8;
        float s1r0 = 0.f, s2r0 = 0.f, s1r1 = 0.f, s2r1 = 0.f;
#pragma unroll
        for (int j = 0; j < 8; ++j) {
            int col = jb + 8 * j + 2 * q;
            if (gn0 < N_) *(float2*)(g_xp + (size_t)gn0 * 128 + col) = make_float2(accC[j][0], accC[j][1]);
            if (gn1 < N_) *(float2*)(g_xp + (size_t)gn1 * 128 + col) = make_float2(accC[j][2], accC[j][3]);
            float as0 = sAS[col], as1 = sAS[col + 1];
            float ad0 = sAD[col], ad1 = sAD[col + 1];
            s1r0 += accC[j][0] * as0 + accC[j][1] * as1;
            s2r0 += accC[j][0] * ad0 + accC[j][1] * ad1;
            s1r1 += accC[j][2] * as0 + accC[j][3] * as1;
            s2r1 += accC[j][2] * ad0 + accC[j][3] * ad1;
        }
        s1r0 += __shfl_xor_sync(0xffffffffu, s1r0, 1); s1r0 += __shfl_xor_sync(0xffffffffu, s1r0, 2);
        s2r0 += __shfl_xor_sync(0xffffffffu, s2r0, 1); s2r0 += __shfl_xor_sync(0xffffffffu, s2r0, 2);
        s1r1 += __shfl_xor_sync(0xffffffffu, s1r1, 1); s1r1 += __shfl_xor_sync(0xffffffffu, s1r1, 2);
        s2r1 += __shfl_xor_sync(0xffffffffu, s2r1, 1); s2r1 += __shfl_xor_sync(0xffffffffu, s2r1, 2);
        if (q == 0) {
            atomicAdd(&sS[m16 + g], s1r0);     atomicAdd(&sD[m16 + g], s2r0);
            atomicAdd(&sS[m16 + g + 8], s1r1); atomicAdd(&sD[m16 + g + 8], s2r1);
        }
    }
    __syncthreads();
    if (tid < 64) {
        int gn = row0 + tid;
        if (gn < N_) { g_asrc[gn] = sS[tid]; g_adst[gn] = sD[tid]; }
    }
}

// ---------------- GAT aggregation: alpha stash + pipelined gather ----------------
__global__ __launch_bounds__(256) void k_gat(const float* __restrict__ gbias) {
    __shared__ double ssum[128], ssq[128];
    __shared__ float stash[8 * 64];
    int tid = threadIdx.x;
    if (tid < 128) { ssum[tid] = 0.0; ssq[tid] = 0.0; }
    __syncthreads();

    int wid = tid >> 5, lane = tid & 31;
    int n = blockIdx.x * 8 + wid;
    if (n < N_) {
        int s0 = g_off[n], s1e = g_off[n + 1];
        int deg = s1e - s0;
        float ad = g_adst[n];
        float* st = stash + wid * 64;

        // pass 1: alpha -> stash (deg<=64 slots), warp max
        float m = -1e30f;
        for (int t = lane; t < deg; t += 32) {
            float a = g_asrc[g_col[s0 + t]] + ad;
            a = (a > 0.f) ? a : NEG * a;
            if (t < 64) st[t] = a;
            m = fmaxf(m, a);
        }
#pragma unroll
        for (int o = 16; o; o >>= 1) m = fmaxf(m, __shfl_xor_sync(0xffffffffu, m, o));

        // pass 2: exp from stash, sum; write exp back
        float se = 0.f;
        for (int t = lane; t < deg; t += 32) {
            float a;
            if (t < 64) a = st[t];
            else {
                a = g_asrc[g_col[s0 + t]] + ad;
                a = (a > 0.f) ? a : NEG * a;
            }
            float e = __expf(a - m);
            if (t < 64) st[t] = e;
            se += e;
        }
#pragma unroll
        for (int o = 16; o; o >>= 1) se += __shfl_xor_sync(0xffffffffu, se, o);
        float inv = 1.f / (se + 1e-16f);
        __syncwarp();

        // gather: 2-deep pipeline, value load prefetched one edge ahead
        float4 acc = make_float4(0.f, 0.f, 0.f, 0.f);
        int   cs = g_col[s0];
        float4 cv = *(const float4*)(g_xp + (size_t)cs * 128 + lane * 4);
        for (int t = 0; t < deg; ++t) {
            int   ns = 0;
            if (t + 1 < deg) ns = g_col[s0 + t + 1];
            float4 nv = *(const float4*)(g_xp + (size_t)ns * 128 + lane * 4);
            float e;
            if (t < 64) e = st[t];                     // warp broadcast
            else {
                float a = g_asrc[cs] + ad;
                a = (a > 0.f) ? a : NEG * a;
                e = __expf(a - m);
            }
            float c = e * inv;
            acc.x = fmaf(c, cv.x, acc.x);
            acc.y = fmaf(c, cv.y, acc.y);
            acc.z = fmaf(c, cv.z, acc.z);
            acc.w = fmaf(c, cv.w, acc.w);
            cs = ns; cv = nv;
        }
        float4 b = *(const float4*)(gbias + lane * 4);
        acc.x += b.x; acc.y += b.y; acc.z += b.z; acc.w += b.w;
        *(float4*)(g_out + (size_t)n * 128 + lane * 4) = acc;

        int f = lane * 4;
        atomicAdd(&ssum[f + 0], (double)acc.x);
        atomicAdd(&ssum[f + 1], (double)acc.y);
        atomicAdd(&ssum[f + 2], (double)acc.z);
        atomicAdd(&ssum[f + 3], (double)acc.w);
        atomicAdd(&ssq[f + 0], (double)acc.x * (double)acc.x);
        atomicAdd(&ssq[f + 1], (double)acc.y * (double)acc.y);
        atomicAdd(&ssq[f + 2], (double)acc.z * (double)acc.z);
        atomicAdd(&ssq[f + 3], (double)acc.w * (double)acc.w);
    }
    __syncthreads();
    if (tid < 128) {
        atomicAdd(&g_colsum[tid], ssum[tid]);
        atomicAdd(&g_colsq[tid], ssq[tid]);
    }
}

// ---------------- GraphNorm stats ----------------
__global__ void k_stats(const float* __restrict__ gnw, const float* __restrict__ gnb,
                        const float* __restrict__ gnms) {
    int f = threadIdx.x;
    if (f < 128) {
        double m = g_colsum[f] / (double)N_;
        double q = g_colsq[f] / (double)N_;
        double s = (double)gnms[f];
        double var = q - 2.0 * s * m * m + s * s * m * m;
        float inv = (float)(1.0 / sqrt(var + (double)EPSN));
        float sc = gnw[f] * inv;
        g_nscale[f] = sc;
        g_nshift[f] = gnb[f] - (float)(s * m) * sc;
    }
}

// ---------------- final kernel (tensor-core) ----------------
#define SMEM_FINAL ((64*130*4) * 4 + (128*2 + 64) * 4)

__global__ __launch_bounds__(256, 1) void k_final(
    const float* __restrict__ x,
    const float* __restrict__ Wc0, const float* __restrict__ bc0,
    const float* __restrict__ Wc1, const float* __restrict__ bc1,
    const void* __restrict__ mask,
    float* __restrict__ out)
{
    extern __shared__ unsigned smu[];
    unsigned* XCh = smu;
    unsigned* XCl = XCh + 64 * 130;
    unsigned* Wh  = XCl + 64 * 130;
    unsigned* Wl  = Wh + 64 * 130;
    float* nsc = (float*)(Wl + 64 * 130);
    float* nsh = nsc + 128;
    float* cz  = nsh + 128;

    int tid = threadIdx.x;
    int row0 = blockIdx.x * 64;

    if (tid < 128) { nsc[tid] = g_nscale[tid]; nsh[tid] = g_nshift[tid]; }
    if (tid < 64) {
        int gn = row0 + tid;
        cz[tid] = (gn < N_ && ld_mask(mask, gn)) ? ZMIX : (1.f - ZMIX);
    }
    __syncthreads();

    for (int p = tid; p < 64 * 128; p += 256) {
        int n = p >> 7, kp = p & 127;
        int col = 2 * kp;
        int gn = row0 + n;
        float v0 = 0.f, v1 = 0.f;
        if (gn < N_) {
            if (col < 128) {
                float2 t = *(const float2*)(g_out + (size_t)gn * 128 + col);
                v0 = t.x * nsc[col] + nsh[col];
                v1 = t.y * nsc[col + 1] + nsh[col + 1];
            } else {
                float2 t = *(const float2*)(x + (size_t)gn * 128 + col - 128);
                v0 = t.x; v1 = t.y;
            }
        }
        unsigned h, l; split2(v0, v1, h, l);
        XCh[n * 130 + kp] = h; XCl[n * 130 + kp] = l;
    }

    int lane = tid & 31, w = tid >> 5;
    int g = lane >> 2, q = lane & 3;
    int m16 = (w >> 1) * 16;
    int nb  = (w & 1) * 32;
    int ra = (m16 + g) * 130 + q;
    int rb = (m16 + g + 8) * 130 + q;
    int jbg = nb + g;

    for (int jc = 0; jc < 2; ++jc) {
        int jbase = jc * 64;
        __syncthreads();
        for (int p = tid; p < 64 * 128; p += 256) {
            int j = p >> 7, kp = p & 127;
            float2 v = *(const float2*)(Wc1 + (size_t)(jbase + j) * 256 + 2 * kp);
            unsigned h, l; split2(v.x, v.y, h, l);
            Wh[j * 130 + kp] = h; Wl[j * 130 + kp] = l;
        }
        __syncthreads();
        float acc1[4][4];
#pragma unroll
        for (int j = 0; j < 4; ++j) {
            float2 bv = *(const float2*)(bc1 + jbase + nb + 8 * j + 2 * q);
            acc1[j][0] = bv.x; acc1[j][1] = bv.y; acc1[j][2] = bv.x; acc1[j][3] = bv.y;
        }
        wgemm<16, 4, 130>(XCh, XCl, Wh, Wl, acc1, ra, rb, jbg, q);

        __syncthreads();
        for (int p = tid; p < 64 * 128; p += 256) {
            int j = p >> 7, kp = p & 127;
            float2 v = *(const float2*)(Wc0 + (size_t)(jbase + j) * 256 + 2 * kp);
            unsigned h, l; split2(v.x, v.y, h, l);
            Wh[j * 130 + kp] = h; Wl[j * 130 + kp] = l;
        }
        __syncthreads();
        float acc0[4][4];
#pragma unroll
        for (int j = 0; j < 4; ++j) {
            float2 bv = *(const float2*)(bc0 + jbase + nb + 8 * j + 2 * q);
            acc0[j][0] = bv.x; acc0[j][1] = bv.y; acc0[j][2] = bv.x; acc0[j][3] = bv.y;
        }
        wgemm<16, 4, 130>(XCh, XCl, Wh, Wl, acc0, ra, rb, jbg, q);

        {
            float c0 = cz[m16 + g], c1 = cz[m16 + g + 8];
            int gn0 = row0 + m16 + g, gn1 = gn0 + 8;
#pragma unroll
            for (int j = 0; j < 4; ++j) {
                int col = jbase + nb + 8 * j + 2 * q;
                if (gn0 < N_) {
                    float2 r;
                    r.x = c0 * acc1[j][0] + (1.f - c0) * acc0[j][0];
                    r.y = c0 * acc1[j][1] + (1.f - c0) * acc0[j][1];
                    *(float2*)(out + (size_t)gn0 * 128 + col) = r;
                }
                if (gn1 < N_) {
                    float2 r;
                    r.x = c1 * acc1[j][2] + (1.f - c1) * acc0[j][2];
                    r.y = c1 * acc1[j][3] + (1.f - c1) * acc0[j][3];
                    *(float2*)(out + (size_t)gn1 * 128 + col) = r;
                }
            }
        }
    }
}

// ---------------- launch ----------------
// NOTE: k_node kept at 4th launch position — the ncu capture window has
// empirically landed on the 4th launch (k_scan1 in R3/R6); k_node only
// depends on k_detect, so this is dependency-safe and gets us a profile
// of the tensor-core GEMM kernel.
extern "C" void kernel_launch(void* const* d_in, const int* in_sizes, int n_in,
                              void* d_out, int out_size) {
    const float* x    = (const float*)d_in[0];
    const float* Wt0  = (const float*)d_in[2];
    const float* bt0  = (const float*)d_in[3];
    const float* Wt1  = (const float*)d_in[4];
    const float* bt1  = (const float*)d_in[5];
    const float* gW   = (const float*)d_in[6];
    const float* atts = (const float*)d_in[7];
    const float* attd = (const float*)d_in[8];
    const float* gbias= (const float*)d_in[9];
    const float* gnw  = (const float*)d_in[10];
    const float* gnb  = (const float*)d_in[11];
    const float* gnms = (const float*)d_in[12];
    const float* Wc0  = (const float*)d_in[13];
    const float* bc0  = (const float*)d_in[14];
    const float* Wc1  = (const float*)d_in[15];
    const float* bc1  = (const float*)d_in[16];
    const void*  ei   = d_in[17];
    const void*  mask = d_in[18];
    float* out = (float*)d_out;

    cudaFuncSetAttribute(k_node,  cudaFuncAttributeMaxDynamicSharedMemorySize, SMEM_NODE);
    cudaFuncSetAttribute(k_final, cudaFuncAttributeMaxDynamicSharedMemorySize, SMEM_FINAL);

    const int NB_SCAN = (N_ + 1023) / 1024;

    k_detect   <<<1, 32>>>(ei, mask);
    k_zero     <<<(N_ + 255) / 256, 256>>>();
    k_hist     <<<(E_ + 255) / 256, 256>>>(ei);
    k_node     <<<(N_ + 63) / 64, 256, SMEM_NODE>>>(x, Wt0, bt0, Wt1, bt1, gW, atts, attd, mask);
    k_scan1    <<<NB_SCAN, 1024>>>();
    k_scan2    <<<1, 32>>>(NB_SCAN);
    k_scan3    <<<NB_SCAN, 1024>>>();
    k_fillself <<<(N_ + 255) / 256, 256>>>();
    k_filledges<<<(E_ + 255) / 256, 256>>>(ei);
    k_gat      <<<(N_ + 7) / 8, 256>>>(gbias);
    k_stats    <<<1, 128>>>(gnw, gnb, gnms);
    k_final    <<<(N_ + 63) / 64, 256, SMEM_FINAL>>>(x, Wc0, bc0, Wc1, bc1, mask, out);
}

// round 9
// speedup vs baseline: 1.7149x; 1.0957x over previous
#include <cuda_runtime.h>
#include <cuda_bf16.h>
#include <math.h>

#define N_    100000
#define E_    1600000
#define ZMIX  0.8f
#define NEG   0.2f
#define EPSN  1e-5

// ---------------- device scratch (static globals; no allocation) ----------------
__device__ float  g_xp [(size_t)N_ * 128];
__device__ float  g_out[(size_t)N_ * 128];
__device__ float  g_asrc[N_];
__device__ float  g_adst[N_];
__device__ int    g_deg[N_];
__device__ int    g_off[N_ + 1];
__device__ int    g_cursor[N_];
__device__ int    g_col[E_ + N_];
__device__ int    g_bsum[128];
__device__ double g_colsum[128];
__device__ double g_colsq[128];
__device__ float  g_nscale[128];
__device__ float  g_nshift[128];
__device__ int    g_ei64;
__device__ int    g_mask4;

// ---------------- dtype detection ----------------
__global__ void k_detect(const void* ei, const void* mask) {
    int lane = threadIdx.x;
    const int* w = (const int*)ei;
    int nz = 0;
    for (int k = lane; k < 512; k += 32) nz |= (w[2 * k + 1] != 0);
    const unsigned char* mb = (const unsigned char*)mask;
    int mnz = 0;
    for (int k = lane; k < 500; k += 32) {
        int o = k * 196 + (k % 3) + 1;
        mnz |= (mb[o] != 0);
    }
    nz  = __any_sync(0xffffffffu, nz);
    mnz = __any_sync(0xffffffffu, mnz);
    if (lane == 0) { g_ei64 = !nz; g_mask4 = !mnz; }
}

__device__ __forceinline__ int ld_ei(const void* ei, size_t idx) {
    long long v = g_ei64 ? ((const long long*)ei)[idx]
                         : (long long)((const int*)ei)[idx];
    int t = (int)v;
    if (t < 0) t = 0;
    if (t >= N_) t = N_ - 1;
    return t;
}

__device__ __forceinline__ int ld_mask(const void* m, int i) {
    return g_mask4 ? (((const int*)m)[i] != 0) : (((const unsigned char*)m)[i] != 0);
}

// ---------------- CSR build ----------------
__global__ void k_zero() {
    int i = blockIdx.x * blockDim.x + threadIdx.x;
    if (i < N_) g_deg[i] = 1;
    if (i < 128) { g_colsum[i] = 0.0; g_colsq[i] = 0.0; }
}

__global__ void k_hist(const void* __restrict__ ei) {
    int e = blockIdx.x * blockDim.x + threadIdx.x;
    if (e < E_) atomicAdd(&g_deg[ld_ei(ei, (size_t)E_ + e)], 1);
}

__global__ void k_scan1() {
    __shared__ int s[1024];
    int tid = threadIdx.x;
    int g = blockIdx.x * 1024 + tid;
    int v = (g < N_) ? g_deg[g] : 0;
    s[tid] = v;
    __syncthreads();
    for (int o = 1; o < 1024; o <<= 1) {
        int t = (tid >= o) ? s[tid - o] : 0;
        __syncthreads();
        s[tid] += t;
        __syncthreads();
    }
    if (g < N_) g_off[g] = s[tid] - v;
    if (tid == 1023) g_bsum[blockIdx.x] = s[1023];
}

__global__ void k_scan2(int nb) {
    if (threadIdx.x == 0) {
        int r = 0;
        for (int b = 0; b < nb; b++) { int t = g_bsum[b]; g_bsum[b] = r; r += t; }
    }
}

__global__ void k_scan3() {
    int tid = threadIdx.x;
    int g = blockIdx.x * 1024 + tid;
    if (g < N_) g_off[g] += g_bsum[blockIdx.x];
    if (g == 0) g_off[N_] = N_ + E_;
}

__global__ void k_fillself() {
    int i = blockIdx.x * blockDim.x + threadIdx.x;
    if (i < N_) { int o = g_off[i]; g_col[o] = i; g_cursor[i] = o + 1; }
}

__global__ void k_filledges(const void* __restrict__ ei) {
    int e = blockIdx.x * blockDim.x + threadIdx.x;
    if (e < E_) {
        int d = ld_ei(ei, (size_t)E_ + e);
        int p = atomicAdd(&g_cursor[d], 1);
        g_col[p] = ld_ei(ei, e);
    }
}

// ---------------- bf16x3 mma building blocks ----------------
__device__ __forceinline__ unsigned pack2(float x0, float x1) {
    __nv_bfloat162 v = __floats2bfloat162_rn(x0, x1);
    return *reinterpret_cast<unsigned*>(&v);
}

__device__ __forceinline__ void split2(float x0, float x1, unsigned &h, unsigned &l) {
    float h0 = __bfloat162float(__float2bfloat16(x0));
    float h1 = __bfloat162float(__float2bfloat16(x1));
    h = pack2(x0, x1);
    l = pack2(x0 - h0, x1 - h1);
}

__device__ __forceinline__ void mma4(float* c,
    unsigned a0, unsigned a1, unsigned a2, unsigned a3, unsigned b0, unsigned b1) {
    asm volatile(
        "mma.sync.aligned.m16n8k16.row.col.f32.bf16.bf16.f32 "
        "{%0,%1,%2,%3}, {%4,%5,%6,%7}, {%8,%9}, {%0,%1,%2,%3};\n"
        : "+f"(c[0]), "+f"(c[1]), "+f"(c[2]), "+f"(c[3])
        : "r"(a0), "r"(a1), "r"(a2), "r"(a3), "r"(b0), "r"(b1));
}

// warp-tile GEMM: KS k16-steps, NT 8-col ntiles, W = u32 row width of operand tiles.
// W chosen so (W*g + q) mod 32 is distinct across the warp -> conflict-free LDS.
template<int KS, int NT, int W>
__device__ __forceinline__ void wgemm(const unsigned* __restrict__ Ah, const unsigned* __restrict__ Al,
                                      const unsigned* __restrict__ Bh, const unsigned* __restrict__ Bl,
                                      float (*acc)[4], int ra, int rb, int jbg, int q) {
    for (int ks = 0; ks < KS; ++ks) {
        int o = ks * 8;
        unsigned ah0 = Ah[ra + o], ah1 = Ah[rb + o], ah2 = Ah[ra + o + 4], ah3 = Ah[rb + o + 4];
        unsigned al0 = Al[ra + o], al1 = Al[rb + o], al2 = Al[ra + o + 4], al3 = Al[rb + o + 4];
#pragma unroll
        for (int j = 0; j < NT; ++j) {
            int bo = (jbg + 8 * j) * W + q + o;
            unsigned bh0 = Bh[bo], bh1 = Bh[bo + 4];
            unsigned bl0 = Bl[bo], bl1 = Bl[bo + 4];
            mma4(acc[j], ah0, ah1, ah2, ah3, bh0, bh1);
            mma4(acc[j], ah0, ah1, ah2, ah3, bl0, bl1);
            mma4(acc[j], al0, al1, al2, al3, bh0, bh1);
        }
    }
}

// ---------------- fused node kernel (tensor-core, 512 thr, W=68 conflict-free) ----------------
#define WN 68
#define SMEM_NODE ((64*WN*2 + 128*WN*2) * 4 + (128*2 + 64*3) * 4)

__global__ __launch_bounds__(512, 1) void k_node(
    const float* __restrict__ x,
    const float* __restrict__ Wt0g, const float* __restrict__ bt0,
    const float* __restrict__ Wt1g, const float* __restrict__ bt1,
    const float* __restrict__ gWg,
    const float* __restrict__ atts, const float* __restrict__ attd,
    const void* __restrict__ mask)
{
    extern __shared__ unsigned smu[];
    unsigned* Ah = smu;
    unsigned* Al = Ah + 64 * WN;
    unsigned* Wh = Al + 64 * WN;
    unsigned* Wl = Wh + 128 * WN;
    float* sAS = (float*)(Wl + 128 * WN);
    float* sAD = sAS + 128;
    float* sS  = sAD + 128;
    float* sD  = sS + 64;
    float* cz  = sD + 64;

    int tid = threadIdx.x;
    int row0 = blockIdx.x * 64;

    for (int p = tid; p < 64 * 64; p += 512) {
        int n = p >> 6, kp = p & 63;
        int gn = row0 + n;
        float2 v = make_float2(0.f, 0.f);
        if (gn < N_) v = *(const float2*)(x + (size_t)gn * 128 + 2 * kp);
        unsigned h, l; split2(v.x, v.y, h, l);
        Ah[n * WN + kp] = h; Al[n * WN + kp] = l;
    }
    if (tid < 128) { sAS[tid] = atts[tid]; sAD[tid] = attd[tid]; }
    if (tid < 64) {
        sS[tid] = 0.f; sD[tid] = 0.f;
        int gn = row0 + tid;
        cz[tid] = (gn < N_ && ld_mask(mask, gn)) ? ZMIX : (1.f - ZMIX);
    }
    for (int p = tid; p < 128 * 64; p += 512) {
        int j = p >> 6, kp = p & 63;
        float2 v = *(const float2*)(Wt1g + (size_t)j * 128 + 2 * kp);
        unsigned h, l; split2(v.x, v.y, h, l);
        Wh[j * WN + kp] = h; Wl[j * WN + kp] = l;
    }
    __syncthreads();

    int lane = tid & 31, w = tid >> 5;           // 16 warps
    int g = lane >> 2, q = lane & 3;
    int m16 = (w >> 2) * 16;                      // 4 row-groups
    int jb  = (w & 3) * 32;                       // 4 col-chunks of 32
    int ra = (m16 + g) * WN + q;
    int rb = (m16 + g + 8) * WN + q;
    int jbg = jb + g;

    // phase A: h1 = x W1^T + b1
    float accA[4][4];
#pragma unroll
    for (int j = 0; j < 4; ++j) {
        float2 bv = *(const float2*)(bt1 + jb + 8 * j + 2 * q);
        accA[j][0] = bv.x; accA[j][1] = bv.y; accA[j][2] = bv.x; accA[j][3] = bv.y;
    }
    wgemm<8, 4, WN>(Ah, Al, Wh, Wl, accA, ra, rb, jbg, q);

    // phase B: load W_t0, h0 = x W0^T + b0
    __syncthreads();
    for (int p = tid; p < 128 * 64; p += 512) {
        int j = p >> 6, kp = p & 63;
        float2 v = *(const float2*)(Wt0g + (size_t)j * 128 + 2 * kp);
        unsigned h, l; split2(v.x, v.y, h, l);
        Wh[j * WN + kp] = h; Wl[j * WN + kp] = l;
    }
    __syncthreads();
    float accB[4][4];
#pragma unroll
    for (int j = 0; j < 4; ++j) {
        float2 bv = *(const float2*)(bt0 + jb + 8 * j + 2 * q);
        accB[j][0] = bv.x; accB[j][1] = bv.y; accB[j][2] = bv.x; accB[j][3] = bv.y;
    }
    wgemm<8, 4, WN>(Ah, Al, Wh, Wl, accB, ra, rb, jbg, q);
    __syncthreads();

    // mix -> Xb, store bf16 hi/lo into Ah/Al
    {
        float c0 = cz[m16 + g], c1 = cz[m16 + g + 8];
#pragma unroll
        for (int j = 0; j < 4; ++j) {
            int colp = (jb >> 1) + 4 * j + q;
            float xb0 = c0 * fmaxf(accA[j][0], 0.f) + (1.f - c0) * fmaxf(accB[j][0], 0.f);
            float xb1 = c0 * fmaxf(accA[j][1], 0.f) + (1.f - c0) * fmaxf(accB[j][1], 0.f);
            float xb2 = c1 * fmaxf(accA[j][2], 0.f) + (1.f - c1) * fmaxf(accB[j][2], 0.f);
            float xb3 = c1 * fmaxf(accA[j][3], 0.f) + (1.f - c1) * fmaxf(accB[j][3], 0.f);
            unsigned h, l;
            split2(xb0, xb1, h, l);
            Ah[(m16 + g) * WN + colp] = h; Al[(m16 + g) * WN + colp] = l;
            split2(xb2, xb3, h, l);
            Ah[(m16 + g + 8) * WN + colp] = h; Al[(m16 + g + 8) * WN + colp] = l;
        }
    }
    __syncthreads();
    // phase C: load gat_W, xp = Xb gW^T
    for (int p = tid; p < 128 * 64; p += 512) {
        int j = p >> 6, kp = p & 63;
        float2 v = *(const float2*)(gWg + (size_t)j * 128 + 2 * kp);
        unsigned h, l; split2(v.x, v.y, h, l);
        Wh[j * WN + kp] = h; Wl[j * WN + kp] = l;
    }
    __syncthreads();
    float accC[4][4];
#pragma unroll
    for (int j = 0; j < 4; ++j) { accC[j][0] = accC[j][1] = accC[j][2] = accC[j][3] = 0.f; }
    wgemm<8, 4, WN>(Ah, Al, Wh, Wl, accC, ra, rb, jbg, q);

    // epilogue: store xp + att dots (4 warps share each row-group; sS/sD atomics combine)
    {
        int gn0 = row0 + m16 + g, gn1 = gn0 + 8;
        float s1r0 = 0.f, s2r0 = 0.f, s1r1 = 0.f, s2r1 = 0.f;
#pragma unroll
        for (int j = 0; j < 4; ++j) {
            int col = jb + 8 * j + 2 * q;
            if (gn0 < N_) *(float2*)(g_xp + (size_t)gn0 * 128 + col) = make_float2(accC[j][0], accC[j][1]);
            if (gn1 < N_) *(float2*)(g_xp + (size_t)gn1 * 128 + col) = make_float2(accC[j][2], accC[j][3]);
            float as0 = sAS[col], as1 = sAS[col + 1];
            float ad0 = sAD[col], ad1 = sAD[col + 1];
            s1r0 += accC[j][0] * as0 + accC[j][1] * as1;
            s2r0 += accC[j][0] * ad0 + accC[j][1] * ad1;
            s1r1 += accC[j][2] * as0 + accC[j][3] * as1;
            s2r1 += accC[j][2] * ad0 + accC[j][3] * ad1;
        }
        s1r0 += __shfl_xor_sync(0xffffffffu, s1r0, 1); s1r0 += __shfl_xor_sync(0xffffffffu, s1r0, 2);
        s2r0 += __shfl_xor_sync(0xffffffffu, s2r0, 1); s2r0 += __shfl_xor_sync(0xffffffffu, s2r0, 2);
        s1r1 += __shfl_xor_sync(0xffffffffu, s1r1, 1); s1r1 += __shfl_xor_sync(0xffffffffu, s1r1, 2);
        s2r1 += __shfl_xor_sync(0xffffffffu, s2r1, 1); s2r1 += __shfl_xor_sync(0xffffffffu, s2r1, 2);
        if (q == 0) {
            atomicAdd(&sS[m16 + g], s1r0);     atomicAdd(&sD[m16 + g], s2r0);
            atomicAdd(&sS[m16 + g + 8], s1r1); atomicAdd(&sD[m16 + g + 8], s2r1);
        }
    }
    __syncthreads();
    if (tid < 64) {
        int gn = row0 + tid;
        if (gn < N_) { g_asrc[gn] = sS[tid]; g_adst[gn] = sD[tid]; }
    }
}

// ---------------- GAT aggregation: alpha stash + pipelined gather ----------------
__global__ __launch_bounds__(256) void k_gat(const float* __restrict__ gbias) {
    __shared__ double ssum[128], ssq[128];
    __shared__ float stash[8 * 64];
    int tid = threadIdx.x;
    if (tid < 128) { ssum[tid] = 0.0; ssq[tid] = 0.0; }
    __syncthreads();

    int wid = tid >> 5, lane = tid & 31;
    int n = blockIdx.x * 8 + wid;
    if (n < N_) {
        int s0 = g_off[n], s1e = g_off[n + 1];
        int deg = s1e - s0;
        float ad = g_adst[n];
        float* st = stash + wid * 64;

        float m = -1e30f;
        for (int t = lane; t < deg; t += 32) {
            float a = g_asrc[g_col[s0 + t]] + ad;
            a = (a > 0.f) ? a : NEG * a;
            if (t < 64) st[t] = a;
            m = fmaxf(m, a);
        }
#pragma unroll
        for (int o = 16; o; o >>= 1) m = fmaxf(m, __shfl_xor_sync(0xffffffffu, m, o));

        float se = 0.f;
        for (int t = lane; t < deg; t += 32) {
            float a;
            if (t < 64) a = st[t];
            else {
                a = g_asrc[g_col[s0 + t]] + ad;
                a = (a > 0.f) ? a : NEG * a;
            }
            float e = __expf(a - m);
            if (t < 64) st[t] = e;
            se += e;
        }
#pragma unroll
        for (int o = 16; o; o >>= 1) se += __shfl_xor_sync(0xffffffffu, se, o);
        float inv = 1.f / (se + 1e-16f);
        __syncwarp();

        float4 acc = make_float4(0.f, 0.f, 0.f, 0.f);
        int   cs = g_col[s0];
        float4 cv = *(const float4*)(g_xp + (size_t)cs * 128 + lane * 4);
        for (int t = 0; t < deg; ++t) {
            int   ns = 0;
            if (t + 1 < deg) ns = g_col[s0 + t + 1];
            float4 nv = *(const float4*)(g_xp + (size_t)ns * 128 + lane * 4);
            float e;
            if (t < 64) e = st[t];
            else {
                float a = g_asrc[cs] + ad;
                a = (a > 0.f) ? a : NEG * a;
                e = __expf(a - m);
            }
            float c = e * inv;
            acc.x = fmaf(c, cv.x, acc.x);
            acc.y = fmaf(c, cv.y, acc.y);
            acc.z = fmaf(c, cv.z, acc.z);
            acc.w = fmaf(c, cv.w, acc.w);
            cs = ns; cv = nv;
        }
        float4 b = *(const float4*)(gbias + lane * 4);
        acc.x += b.x; acc.y += b.y; acc.z += b.z; acc.w += b.w;
        *(float4*)(g_out + (size_t)n * 128 + lane * 4) = acc;

        int f = lane * 4;
        atomicAdd(&ssum[f + 0], (double)acc.x);
        atomicAdd(&ssum[f + 1], (double)acc.y);
        atomicAdd(&ssum[f + 2], (double)acc.z);
        atomicAdd(&ssum[f + 3], (double)acc.w);
        atomicAdd(&ssq[f + 0], (double)acc.x * (double)acc.x);
        atomicAdd(&ssq[f + 1], (double)acc.y * (double)acc.y);
        atomicAdd(&ssq[f + 2], (double)acc.z * (double)acc.z);
        atomicAdd(&ssq[f + 3], (double)acc.w * (double)acc.w);
    }
    __syncthreads();
    if (tid < 128) {
        atomicAdd(&g_colsum[tid], ssum[tid]);
        atomicAdd(&g_colsq[tid], ssq[tid]);
    }
}

// ---------------- GraphNorm stats ----------------
__global__ void k_stats(const float* __restrict__ gnw, const float* __restrict__ gnb,
                        const float* __restrict__ gnms) {
    int f = threadIdx.x;
    if (f < 128) {
        double m = g_colsum[f] / (double)N_;
        double q = g_colsq[f] / (double)N_;
        double s = (double)gnms[f];
        double var = q - 2.0 * s * m * m + s * s * m * m;
        float inv = (float)(1.0 / sqrt(var + (double)EPSN));
        float sc = gnw[f] * inv;
        g_nscale[f] = sc;
        g_nshift[f] = gnb[f] - (float)(s * m) * sc;
    }
}

// ---------------- final kernel (tensor-core, 512 thr, W=132 conflict-free) ----------------
#define WF 132
#define SMEM_FINAL ((64*WF*4) * 4 + (128*2 + 64) * 4)

__global__ __launch_bounds__(512, 1) void k_final(
    const float* __restrict__ x,
    const float* __restrict__ Wc0, const float* __restrict__ bc0,
    const float* __restrict__ Wc1, const float* __restrict__ bc1,
    const void* __restrict__ mask,
    float* __restrict__ out)
{
    extern __shared__ unsigned smu[];
    unsigned* XCh = smu;
    unsigned* XCl = XCh + 64 * WF;
    unsigned* Wh  = XCl + 64 * WF;
    unsigned* Wl  = Wh + 64 * WF;
    float* nsc = (float*)(Wl + 64 * WF);
    float* nsh = nsc + 128;
    float* cz  = nsh + 128;

    int tid = threadIdx.x;
    int row0 = blockIdx.x * 64;

    if (tid < 128) { nsc[tid] = g_nscale[tid]; nsh[tid] = g_nshift[tid]; }
    if (tid < 64) {
        int gn = row0 + tid;
        cz[tid] = (gn < N_ && ld_mask(mask, gn)) ? ZMIX : (1.f - ZMIX);
    }
    __syncthreads();

    for (int p = tid; p < 64 * 128; p += 512) {
        int n = p >> 7, kp = p & 127;
        int col = 2 * kp;
        int gn = row0 + n;
        float v0 = 0.f, v1 = 0.f;
        if (gn < N_) {
            if (col < 128) {
                float2 t = *(const float2*)(g_out + (size_t)gn * 128 + col);
                v0 = t.x * nsc[col] + nsh[col];
                v1 = t.y * nsc[col + 1] + nsh[col + 1];
            } else {
                float2 t = *(const float2*)(x + (size_t)gn * 128 + col - 128);
                v0 = t.x; v1 = t.y;
            }
        }
        unsigned h, l; split2(v0, v1, h, l);
        XCh[n * WF + kp] = h; XCl[n * WF + kp] = l;
    }

    int lane = tid & 31, w = tid >> 5;           // 16 warps
    int g = lane >> 2, q = lane & 3;
    int m16 = (w >> 2) * 16;                      // 4 row-groups
    int nbw = (w & 3) * 16;                       // 4 col-chunks of 16 within the 64-col jc chunk
    int ra = (m16 + g) * WF + q;
    int rb = (m16 + g + 8) * WF + q;
    int jbg = nbw + g;

    for (int jc = 0; jc < 2; ++jc) {
        int jbase = jc * 64;
        __syncthreads();
        for (int p = tid; p < 64 * 128; p += 512) {
            int j = p >> 7, kp = p & 127;
            float2 v = *(const float2*)(Wc1 + (size_t)(jbase + j) * 256 + 2 * kp);
            unsigned h, l; split2(v.x, v.y, h, l);
            Wh[j * WF + kp] = h; Wl[j * WF + kp] = l;
        }
        __syncthreads();
        float acc1[2][4];
#pragma unroll
        for (int j = 0; j < 2; ++j) {
            float2 bv = *(const float2*)(bc1 + jbase + nbw + 8 * j + 2 * q);
            acc1[j][0] = bv.x; acc1[j][1] = bv.y; acc1[j][2] = bv.x; acc1[j][3] = bv.y;
        }
        wgemm<16, 2, WF>(XCh, XCl, Wh, Wl, acc1, ra, rb, jbg, q);

        __syncthreads();
        for (int p = tid; p < 64 * 128; p += 512) {
            int j = p >> 7, kp = p & 127;
            float2 v = *(const float2*)(Wc0 + (size_t)(jbase + j) * 256 + 2 * kp);
            unsigned h, l; split2(v.x, v.y, h, l);
            Wh[j * WF + kp] = h; Wl[j * WF + kp] = l;
        }
        __syncthreads();
        float acc0[2][4];
#pragma unroll
        for (int j = 0; j < 2; ++j) {
            float2 bv = *(const float2*)(bc0 + jbase + nbw + 8 * j + 2 * q);
            acc0[j][0] = bv.x; acc0[j][1] = bv.y; acc0[j][2] = bv.x; acc0[j][3] = bv.y;
        }
        wgemm<16, 2, WF>(XCh, XCl, Wh, Wl, acc0, ra, rb, jbg, q);

        {
            float c0 = cz[m16 + g], c1 = cz[m16 + g + 8];
            int gn0 = row0 + m16 + g, gn1 = gn0 + 8;
#pragma unroll
            for (int j = 0; j < 2; ++j) {
                int col = jbase + nbw + 8 * j + 2 * q;
                if (gn0 < N_) {
                    float2 r;
                    r.x = c0 * acc1[j][0] + (1.f - c0) * acc0[j][0];
                    r.y = c0 * acc1[j][1] + (1.f - c0) * acc0[j][1];
                    *(float2*)(out + (size_t)gn0 * 128 + col) = r;
                }
                if (gn1 < N_) {
                    float2 r;
                    r.x = c1 * acc1[j][2] + (1.f - c1) * acc0[j][2];
                    r.y = c1 * acc1[j][3] + (1.f - c1) * acc0[j][3];
                    *(float2*)(out + (size_t)gn1 * 128 + col) = r;
                }
            }
        }
    }
}

// ---------------- launch ----------------
extern "C" void kernel_launch(void* const* d_in, const int* in_sizes, int n_in,
                              void* d_out, int out_size) {
    const float* x    = (const float*)d_in[0];
    const float* Wt0  = (const float*)d_in[2];
    const float* bt0  = (const float*)d_in[3];
    const float* Wt1  = (const float*)d_in[4];
    const float* bt1  = (const float*)d_in[5];
    const float* gW   = (const float*)d_in[6];
    const float* atts = (const float*)d_in[7];
    const float* attd = (const float*)d_in[8];
    const float* gbias= (const float*)d_in[9];
    const float* gnw  = (const float*)d_in[10];
    const float* gnb  = (const float*)d_in[11];
    const float* gnms = (const float*)d_in[12];
    const float* Wc0  = (const float*)d_in[13];
    const float* bc0  = (const float*)d_in[14];
    const float* Wc1  = (const float*)d_in[15];
    const float* bc1  = (const float*)d_in[16];
    const void*  ei   = d_in[17];
    const void*  mask = d_in[18];
    float* out = (float*)d_out;

    cudaFuncSetAttribute(k_node,  cudaFuncAttributeMaxDynamicSharedMemorySize, SMEM_NODE);
    cudaFuncSetAttribute(k_final, cudaFuncAttributeMaxDynamicSharedMemorySize, SMEM_FINAL);

    const int NB_SCAN = (N_ + 1023) / 1024;

    k_detect   <<<1, 32>>>(ei, mask);
    k_zero     <<<(N_ + 255) / 256, 256>>>();
    k_hist     <<<(E_ + 255) / 256, 256>>>(ei);
    k_node     <<<(N_ + 63) / 64, 512, SMEM_NODE>>>(x, Wt0, bt0, Wt1, bt1, gW, atts, attd, mask);
    k_scan1    <<<NB_SCAN, 1024>>>();
    k_scan2    <<<1, 32>>>(NB_SCAN);
    k_scan3    <<<NB_SCAN, 1024>>>();
    k_fillself <<<(N_ + 255) / 256, 256>>>();
    k_filledges<<<(E_ + 255) / 256, 256>>>(ei);
    k_gat      <<<(N_ + 7) / 8, 256>>>(gbias);
    k_stats    <<<1, 128>>>(gnw, gnb, gnms);
    k_final    <<<(N_ + 63) / 64, 512, SMEM_FINAL>>>(x, Wc0, bc0, Wc1, bc1, mask, out);
}

// round 11
// speedup vs baseline: 2.0056x; 1.1695x over previous
#include <cuda_runtime.h>
#include <cuda_bf16.h>
#include <math.h>

#define N_    100000
#define E_    1600000
#define ZMIX  0.8f
#define NEG   0.2f
#define EPSN  1e-5

// ---------------- device scratch (static globals; no allocation) ----------------
__device__ float  g_xp [(size_t)N_ * 128];
__device__ float  g_out[(size_t)N_ * 128];
__device__ float  g_asrc[N_];
__device__ float  g_adst[N_];
__device__ int    g_deg[N_];
__device__ int    g_off[N_ + 1];
__device__ int    g_cursor[N_];
__device__ int    g_col[E_ + N_];
__device__ int    g_bsum[128];
__device__ double g_colsum[128];
__device__ double g_colsq[128];
__device__ float  g_nscale[128];
__device__ float  g_nshift[128];
__device__ int    g_ei64;
__device__ int    g_mask4;
// pre-split bf16 hi/lo weight images (pair-packed u32)
__device__ unsigned g_w1h[8192],  g_w1l[8192];
__device__ unsigned g_w0h[8192],  g_w0l[8192];
__device__ unsigned g_gwh[8192],  g_gwl[8192];
__device__ unsigned g_c1h[16384], g_c1l[16384];
__device__ unsigned g_c0h[16384], g_c0l[16384];

// ---------------- dtype detection ----------------
__global__ void k_detect(const void* ei, const void* mask) {
    int lane = threadIdx.x;
    const int* w = (const int*)ei;
    int nz = 0;
    for (int k = lane; k < 512; k += 32) nz |= (w[2 * k + 1] != 0);
    const unsigned char* mb = (const unsigned char*)mask;
    int mnz = 0;
    for (int k = lane; k < 500; k += 32) {
        int o = k * 196 + (k % 3) + 1;
        mnz |= (mb[o] != 0);
    }
    nz  = __any_sync(0xffffffffu, nz);
    mnz = __any_sync(0xffffffffu, mnz);
    if (lane == 0) { g_ei64 = !nz; g_mask4 = !mnz; }
}

__device__ __forceinline__ int ld_ei(const void* ei, size_t idx) {
    long long v = g_ei64 ? ((const long long*)ei)[idx]
                         : (long long)((const int*)ei)[idx];
    int t = (int)v;
    if (t < 0) t = 0;
    if (t >= N_) t = N_ - 1;
    return t;
}

__device__ __forceinline__ int ld_mask(const void* m, int i) {
    return g_mask4 ? (((const int*)m)[i] != 0) : (((const unsigned char*)m)[i] != 0);
}

// ---------------- bf16 split helpers ----------------
__device__ __forceinline__ unsigned pack2(float x0, float x1) {
    __nv_bfloat162 v = __floats2bfloat162_rn(x0, x1);
    return *reinterpret_cast<unsigned*>(&v);
}

__device__ __forceinline__ void split2(float x0, float x1, unsigned &h, unsigned &l) {
    float h0 = __bfloat162float(__float2bfloat16(x0));
    float h1 = __bfloat162float(__float2bfloat16(x1));
    h = pack2(x0, x1);
    l = pack2(x0 - h0, x1 - h1);
}

// ---------------- one-shot weight splitter ----------------
__global__ void k_wsplit(const float* __restrict__ W1, const float* __restrict__ W0,
                         const float* __restrict__ gW, const float* __restrict__ C1,
                         const float* __restrict__ C0) {
    int i = blockIdx.x * blockDim.x + threadIdx.x;
    if (i < 8192) {
        float2 v = *(const float2*)(W1 + 2 * (size_t)i);
        split2(v.x, v.y, g_w1h[i], g_w1l[i]);
    } else if (i < 16384) {
        int p = i - 8192;
        float2 v = *(const float2*)(W0 + 2 * (size_t)p);
        split2(v.x, v.y, g_w0h[p], g_w0l[p]);
    } else if (i < 24576) {
        int p = i - 16384;
        float2 v = *(const float2*)(gW + 2 * (size_t)p);
        split2(v.x, v.y, g_gwh[p], g_gwl[p]);
    } else if (i < 40960) {
        int p = i - 24576;
        float2 v = *(const float2*)(C1 + 2 * (size_t)p);
        split2(v.x, v.y, g_c1h[p], g_c1l[p]);
    } else if (i < 57344) {
        int p = i - 40960;
        float2 v = *(const float2*)(C0 + 2 * (size_t)p);
        split2(v.x, v.y, g_c0h[p], g_c0l[p]);
    }
}

// ---------------- CSR build ----------------
__global__ void k_zero() {
    int i = blockIdx.x * blockDim.x + threadIdx.x;
    if (i < N_) g_deg[i] = 1;
    if (i < 128) { g_colsum[i] = 0.0; g_colsq[i] = 0.0; }
}

__global__ void k_hist(const void* __restrict__ ei) {
    int e = blockIdx.x * blockDim.x + threadIdx.x;
    if (e < E_) atomicAdd(&g_deg[ld_ei(ei, (size_t)E_ + e)], 1);
}

__global__ void k_scan1() {
    __shared__ int s[1024];
    int tid = threadIdx.x;
    int g = blockIdx.x * 1024 + tid;
    int v = (g < N_) ? g_deg[g] : 0;
    s[tid] = v;
    __syncthreads();
    for (int o = 1; o < 1024; o <<= 1) {
        int t = (tid >= o) ? s[tid - o] : 0;
        __syncthreads();
        s[tid] += t;
        __syncthreads();
    }
    if (g < N_) g_off[g] = s[tid] - v;
    if (tid == 1023) g_bsum[blockIdx.x] = s[1023];
}

__global__ void k_scan2(int nb) {
    if (threadIdx.x == 0) {
        int r = 0;
        for (int b = 0; b < nb; b++) { int t = g_bsum[b]; g_bsum[b] = r; r += t; }
    }
}

__global__ void k_scan3() {
    int tid = threadIdx.x;
    int g = blockIdx.x * 1024 + tid;
    if (g < N_) g_off[g] += g_bsum[blockIdx.x];
    if (g == 0) g_off[N_] = N_ + E_;
}

__global__ void k_fillself() {
    int i = blockIdx.x * blockDim.x + threadIdx.x;
    if (i < N_) { int o = g_off[i]; g_col[o] = i; g_cursor[i] = o + 1; }
}

__global__ void k_filledges(const void* __restrict__ ei) {
    int e = blockIdx.x * blockDim.x + threadIdx.x;
    if (e < E_) {
        int d = ld_ei(ei, (size_t)E_ + e);
        int p = atomicAdd(&g_cursor[d], 1);
        g_col[p] = ld_ei(ei, e);
    }
}

// ---------------- bf16x3 mma ----------------
__device__ __forceinline__ void mma4(float* c,
    unsigned a0, unsigned a1, unsigned a2, unsigned a3, unsigned b0, unsigned b1) {
    asm volatile(
        "mma.sync.aligned.m16n8k16.row.col.f32.bf16.bf16.f32 "
        "{%0,%1,%2,%3}, {%4,%5,%6,%7}, {%8,%9}, {%0,%1,%2,%3};\n"
        : "+f"(c[0]), "+f"(c[1]), "+f"(c[2]), "+f"(c[3])
        : "r"(a0), "r"(a1), "r"(a2), "r"(a3), "r"(b0), "r"(b1));
}

template<int KS, int NT, int W>
__device__ __forceinline__ void wgemm(const unsigned* __restrict__ Ah, const unsigned* __restrict__ Al,
                                      const unsigned* __restrict__ Bh, const unsigned* __restrict__ Bl,
                                      float (*acc)[4], int ra, int rb, int jbg, int q) {
    for (int ks = 0; ks < KS; ++ks) {
        int o = ks * 8;
        unsigned ah0 = Ah[ra + o], ah1 = Ah[rb + o], ah2 = Ah[ra + o + 4], ah3 = Ah[rb + o + 4];
        unsigned al0 = Al[ra + o], al1 = Al[rb + o], al2 = Al[ra + o + 4], al3 = Al[rb + o + 4];
#pragma unroll
        for (int j = 0; j < NT; ++j) {
            int bo = (jbg + 8 * j) * W + q + o;
            unsigned bh0 = Bh[bo], bh1 = Bh[bo + 4];
            unsigned bl0 = Bl[bo], bl1 = Bl[bo + 4];
            mma4(acc[j], ah0, ah1, ah2, ah3, bh0, bh1);
            mma4(acc[j], ah0, ah1, ah2, ah3, bl0, bl1);
            mma4(acc[j], al0, al1, al2, al3, bh0, bh1);
        }
    }
}

// ---------------- fused node kernel (256 thr, NT=8, W=68 conflict-free, pre-split W) ----------------
#define WN 68
#define SMEM_NODE ((64*WN*2 + 128*WN*2) * 4 + (128*2 + 64*3) * 4)

__global__ __launch_bounds__(256, 1) void k_node(
    const float* __restrict__ x,
    const float* __restrict__ bt0, const float* __restrict__ bt1,
    const float* __restrict__ atts, const float* __restrict__ attd,
    const void* __restrict__ mask)
{
    extern __shared__ unsigned smu[];
    unsigned* Ah = smu;
    unsigned* Al = Ah + 64 * WN;
    unsigned* Wh = Al + 64 * WN;
    unsigned* Wl = Wh + 128 * WN;
    float* sAS = (float*)(Wl + 128 * WN);
    float* sAD = sAS + 128;
    float* sS  = sAD + 128;
    float* sD  = sS + 64;
    float* cz  = sD + 64;

    int tid = threadIdx.x;
    int row0 = blockIdx.x * 64;

    for (int p = tid; p < 64 * 64; p += 256) {
        int n = p >> 6, kp = p & 63;
        int gn = row0 + n;
        float2 v = make_float2(0.f, 0.f);
        if (gn < N_) v = *(const float2*)(x + (size_t)gn * 128 + 2 * kp);
        unsigned h, l; split2(v.x, v.y, h, l);
        Ah[n * WN + kp] = h; Al[n * WN + kp] = l;
    }
    if (tid < 128) { sAS[tid] = atts[tid]; sAD[tid] = attd[tid]; }
    if (tid < 64) {
        sS[tid] = 0.f; sD[tid] = 0.f;
        int gn = row0 + tid;
        cz[tid] = (gn < N_ && ld_mask(mask, gn)) ? ZMIX : (1.f - ZMIX);
    }
    for (int p = tid; p < 8192; p += 256) {
        int j = p >> 6, kp = p & 63;
        Wh[j * WN + kp] = g_w1h[p];
        Wl[j * WN + kp] = g_w1l[p];
    }
    __syncthreads();

    int lane = tid & 31, w = tid >> 5;           // 8 warps
    int g = lane >> 2, q = lane & 3;
    int m16 = (w >> 1) * 16;
    int jb  = (w & 1) * 64;
    int ra = (m16 + g) * WN + q;
    int rb = (m16 + g + 8) * WN + q;
    int jbg = jb + g;

    // phase A: h1 = x W1^T + b1
    float accA[8][4];
#pragma unroll
    for (int j = 0; j < 8; ++j) {
        float2 bv = *(const float2*)(bt1 + jb + 8 * j + 2 * q);
        accA[j][0] = bv.x; accA[j][1] = bv.y; accA[j][2] = bv.x; accA[j][3] = bv.y;
    }
    wgemm<8, 8, WN>(Ah, Al, Wh, Wl, accA, ra, rb, jbg, q);

    // phase B: W_t0
    __syncthreads();
    for (int p = tid; p < 8192; p += 256) {
        int j = p >> 6, kp = p & 63;
        Wh[j * WN + kp] = g_w0h[p];
        Wl[j * WN + kp] = g_w0l[p];
    }
    __syncthreads();
    float accB[8][4];
#pragma unroll
    for (int j = 0; j < 8; ++j) {
        float2 bv = *(const float2*)(bt0 + jb + 8 * j + 2 * q);
        accB[j][0] = bv.x; accB[j][1] = bv.y; accB[j][2] = bv.x; accB[j][3] = bv.y;
    }
    wgemm<8, 8, WN>(Ah, Al, Wh, Wl, accB, ra, rb, jbg, q);
    __syncthreads();

    // mix -> Xb (bf16 hi/lo into Ah/Al)
    {
        float c0 = cz[m16 + g], c1 = cz[m16 + g + 8];
#pragma unroll
        for (int j = 0; j < 8; ++j) {
            int colp = (jb >> 1) + 4 * j + q;
            float xb0 = c0 * fmaxf(accA[j][0], 0.f) + (1.f - c0) * fmaxf(accB[j][0], 0.f);
            float xb1 = c0 * fmaxf(accA[j][1], 0.f) + (1.f - c0) * fmaxf(accB[j][1], 0.f);
            float xb2 = c1 * fmaxf(accA[j][2], 0.f) + (1.f - c1) * fmaxf(accB[j][2], 0.f);
            float xb3 = c1 * fmaxf(accA[j][3], 0.f) + (1.f - c1) * fmaxf(accB[j][3], 0.f);
            unsigned h, l;
            split2(xb0, xb1, h, l);
            Ah[(m16 + g) * WN + colp] = h; Al[(m16 + g) * WN + colp] = l;
            split2(xb2, xb3, h, l);
            Ah[(m16 + g + 8) * WN + colp] = h; Al[(m16 + g + 8) * WN + colp] = l;
        }
    }
    __syncthreads();
    // phase C: gat_W
    for (int p = tid; p < 8192; p += 256) {
        int j = p >> 6, kp = p & 63;
        Wh[j * WN + kp] = g_gwh[p];
        Wl[j * WN + kp] = g_gwl[p];
    }
    __syncthreads();
    float accC[8][4];
#pragma unroll
    for (int j = 0; j < 8; ++j) { accC[j][0] = accC[j][1] = accC[j][2] = accC[j][3] = 0.f; }
    wgemm<8, 8, WN>(Ah, Al, Wh, Wl, accC, ra, rb, jbg, q);

    // epilogue: store xp + att dots
    {
        int gn0 = row0 + m16 + g, gn1 = gn0 + 8;
        float s1r0 = 0.f, s2r0 = 0.f, s1r1 = 0.f, s2r1 = 0.f;
#pragma unroll
        for (int j = 0; j < 8; ++j) {
            int col = jb + 8 * j + 2 * q;
            if (gn0 < N_) *(float2*)(g_xp + (size_t)gn0 * 128 + col) = make_float2(accC[j][0], accC[j][1]);
            if (gn1 < N_) *(float2*)(g_xp + (size_t)gn1 * 128 + col) = make_float2(accC[j][2], accC[j][3]);
            float as0 = sAS[col], as1 = sAS[col + 1];
            float ad0 = sAD[col], ad1 = sAD[col + 1];
            s1r0 += accC[j][0] * as0 + accC[j][1] * as1;
            s2r0 += accC[j][0] * ad0 + accC[j][1] * ad1;
            s1r1 += accC[j][2] * as0 + accC[j][3] * as1;
            s2r1 += accC[j][2] * ad0 + accC[j][3] * ad1;
        }
        s1r0 += __shfl_xor_sync(0xffffffffu, s1r0, 1); s1r0 += __shfl_xor_sync(0xffffffffu, s1r0, 2);
        s2r0 += __shfl_xor_sync(0xffffffffu, s2r0, 1); s2r0 += __shfl_xor_sync(0xffffffffu, s2r0, 2);
        s1r1 += __shfl_xor_sync(0xffffffffu, s1r1, 1); s1r1 += __shfl_xor_sync(0xffffffffu, s1r1, 2);
        s2r1 += __shfl_xor_sync(0xffffffffu, s2r1, 1); s2r1 += __shfl_xor_sync(0xffffffffu, s2r1, 2);
        if (q == 0) {
            atomicAdd(&sS[m16 + g], s1r0);     atomicAdd(&sD[m16 + g], s2r0);
            atomicAdd(&sS[m16 + g + 8], s1r1); atomicAdd(&sD[m16 + g + 8], s2r1);
        }
    }
    __syncthreads();
    if (tid < 64) {
        int gn = row0 + tid;
        if (gn < N_) { g_asrc[gn] = sS[tid]; g_adst[gn] = sD[tid]; }
    }
}

// ---------------- GAT aggregation: alpha stash + pipelined gather ----------------
__global__ __launch_bounds__(256) void k_gat(const float* __restrict__ gbias) {
    __shared__ double ssum[128], ssq[128];
    __shared__ float stash[8 * 64];
    int tid = threadIdx.x;
    if (tid < 128) { ssum[tid] = 0.0; ssq[tid] = 0.0; }
    __syncthreads();

    int wid = tid >> 5, lane = tid & 31;
    int n = blockIdx.x * 8 + wid;
    if (n < N_) {
        int s0 = g_off[n], s1e = g_off[n + 1];
        int deg = s1e - s0;
        float ad = g_adst[n];
        float* st = stash + wid * 64;

        float m = -1e30f;
        for (int t = lane; t < deg; t += 32) {
            float a = g_asrc[g_col[s0 + t]] + ad;
            a = (a > 0.f) ? a : NEG * a;
            if (t < 64) st[t] = a;
            m = fmaxf(m, a);
        }
#pragma unroll
        for (int o = 16; o; o >>= 1) m = fmaxf(m, __shfl_xor_sync(0xffffffffu, m, o));

        float se = 0.f;
        for (int t = lane; t < deg; t += 32) {
            float a;
            if (t < 64) a = st[t];
            else {
                a = g_asrc[g_col[s0 + t]] + ad;
                a = (a > 0.f) ? a : NEG * a;
            }
            float e = __expf(a - m);
            if (t < 64) st[t] = e;
            se += e;
        }
#pragma unroll
        for (int o = 16; o; o >>= 1) se += __shfl_xor_sync(0xffffffffu, se, o);
        float inv = 1.f / (se + 1e-16f);
        __syncwarp();

        float4 acc = make_float4(0.f, 0.f, 0.f, 0.f);
        int   cs = g_col[s0];
        float4 cv = *(const float4*)(g_xp + (size_t)cs * 128 + lane * 4);
        for (int t = 0; t < deg; ++t) {
            int   ns = 0;
            if (t + 1 < deg) ns = g_col[s0 + t + 1];
            float4 nv = *(const float4*)(g_xp + (size_t)ns * 128 + lane * 4);
            float e;
            if (t < 64) e = st[t];
            else {
                float a = g_asrc[cs] + ad;
                a = (a > 0.f) ? a : NEG * a;
                e = __expf(a - m);
            }
            float c = e * inv;
            acc.x = fmaf(c, cv.x, acc.x);
            acc.y = fmaf(c, cv.y, acc.y);
            acc.z = fmaf(c, cv.z, acc.z);
            acc.w = fmaf(c, cv.w, acc.w);
            cs = ns; cv = nv;
        }
        float4 b = *(const float4*)(gbias + lane * 4);
        acc.x += b.x; acc.y += b.y; acc.z += b.z; acc.w += b.w;
        *(float4*)(g_out + (size_t)n * 128 + lane * 4) = acc;

        int f = lane * 4;
        atomicAdd(&ssum[f + 0], (double)acc.x);
        atomicAdd(&ssum[f + 1], (double)acc.y);
        atomicAdd(&ssum[f + 2], (double)acc.z);
        atomicAdd(&ssum[f + 3], (double)acc.w);
        atomicAdd(&ssq[f + 0], (double)acc.x * (double)acc.x);
        atomicAdd(&ssq[f + 1], (double)acc.y * (double)acc.y);
        atomicAdd(&ssq[f + 2], (double)acc.z * (double)acc.z);
        atomicAdd(&ssq[f + 3], (double)acc.w * (double)acc.w);
    }
    __syncthreads();
    if (tid < 128) {
        atomicAdd(&g_colsum[tid], ssum[tid]);
        atomicAdd(&g_colsq[tid], ssq[tid]);
    }
}

// ---------------- GraphNorm stats ----------------
__global__ void k_stats(const float* __restrict__ gnw, const float* __restrict__ gnb,
                        const float* __restrict__ gnms) {
    int f = threadIdx.x;
    if (f < 128) {
        double m = g_colsum[f] / (double)N_;
        double q = g_colsq[f] / (double)N_;
        double s = (double)gnms[f];
        double var = q - 2.0 * s * m * m + s * s * m * m;
        float inv = (float)(1.0 / sqrt(var + (double)EPSN));
        float sc = gnw[f] * inv;
        g_nscale[f] = sc;
        g_nshift[f] = gnb[f] - (float)(s * m) * sc;
    }
}

// ---------------- final kernel (512 thr, W=132 conflict-free, pre-split W) ----------------
#define WF 132
#define SMEM_FINAL ((64*WF*4) * 4 + (128*2 + 64) * 4)

__global__ __launch_bounds__(512, 1) void k_final(
    const float* __restrict__ x,
    const float* __restrict__ bc0, const float* __restrict__ bc1,
    const void* __restrict__ mask,
    float* __restrict__ out)
{
    extern __shared__ unsigned smu[];
    unsigned* XCh = smu;
    unsigned* XCl = XCh + 64 * WF;
    unsigned* Wh  = XCl + 64 * WF;
    unsigned* Wl  = Wh + 64 * WF;
    float* nsc = (float*)(Wl + 64 * WF);
    float* nsh = nsc + 128;
    float* cz  = nsh + 128;

    int tid = threadIdx.x;
    int row0 = blockIdx.x * 64;

    if (tid < 128) { nsc[tid] = g_nscale[tid]; nsh[tid] = g_nshift[tid]; }
    if (tid < 64) {
        int gn = row0 + tid;
        cz[tid] = (gn < N_ && ld_mask(mask, gn)) ? ZMIX : (1.f - ZMIX);
    }
    __syncthreads();

    for (int p = tid; p < 64 * 128; p += 512) {
        int n = p >> 7, kp = p & 127;
        int col = 2 * kp;
        int gn = row0 + n;
        float v0 = 0.f, v1 = 0.f;
        if (gn < N_) {
            if (col < 128) {
                float2 t = *(const float2*)(g_out + (size_t)gn * 128 + col);
                v0 = t.x * nsc[col] + nsh[col];
                v1 = t.y * nsc[col + 1] + nsh[col + 1];
            } else {
                float2 t = *(const float2*)(x + (size_t)gn * 128 + col - 128);
                v0 = t.x; v1 = t.y;
            }
        }
        unsigned h, l; split2(v0, v1, h, l);
        XCh[n * WF + kp] = h; XCl[n * WF + kp] = l;
    }

    int lane = tid & 31, w = tid >> 5;           // 16 warps
    int g = lane >> 2, q = lane & 3;
    int m16 = (w >> 2) * 16;
    int nbw = (w & 3) * 16;
    int ra = (m16 + g) * WF + q;
    int rb = (m16 + g + 8) * WF + q;
    int jbg = nbw + g;

    for (int jc = 0; jc < 2; ++jc) {
        int jbase = jc * 64;
        int wofs  = jc * 8192;          // 64 weight rows × 128 pairs
        __syncthreads();
        for (int p = tid; p < 8192; p += 512) {
            int j = p >> 7, kp = p & 127;
            Wh[j * WF + kp] = g_c1h[wofs + p];
            Wl[j * WF + kp] = g_c1l[wofs + p];
        }
        __syncthreads();
        float acc1[2][4];
#pragma unroll
        for (int j = 0; j < 2; ++j) {
            float2 bv = *(const float2*)(bc1 + jbase + nbw + 8 * j + 2 * q);
            acc1[j][0] = bv.x; acc1[j][1] = bv.y; acc1[j][2] = bv.x; acc1[j][3] = bv.y;
        }
        wgemm<16, 2, WF>(XCh, XCl, Wh, Wl, acc1, ra, rb, jbg, q);

        __syncthreads();
        for (int p = tid; p < 8192; p += 512) {
            int j = p >> 7, kp = p & 127;
            Wh[j * WF + kp] = g_c0h[wofs + p];
            Wl[j * WF + kp] = g_c0l[wofs + p];
        }
        __syncthreads();
        float acc0[2][4];
#pragma unroll
        for (int j = 0; j < 2; ++j) {
            float2 bv = *(const float2*)(bc0 + jbase + nbw + 8 * j + 2 * q);
            acc0[j][0] = bv.x; acc0[j][1] = bv.y; acc0[j][2] = bv.x; acc0[j][3] = bv.y;
        }
        wgemm<16, 2, WF>(XCh, XCl, Wh, Wl, acc0, ra, rb, jbg, q);

        {
            float c0 = cz[m16 + g], c1 = cz[m16 + g + 8];
            int gn0 = row0 + m16 + g, gn1 = gn0 + 8;
#pragma unroll
            for (int j = 0; j < 2; ++j) {
                int col = jbase + nbw + 8 * j + 2 * q;
                if (gn0 < N_) {
                    float2 r;
                    r.x = c0 * acc1[j][0] + (1.f - c0) * acc0[j][0];
                    r.y = c0 * acc1[j][1] + (1.f - c0) * acc0[j][1];
                    *(float2*)(out + (size_t)gn0 * 128 + col) = r;
                }
                if (gn1 < N_) {
                    float2 r;
                    r.x = c1 * acc1[j][2] + (1.f - c1) * acc0[j][2];
                    r.y = c1 * acc1[j][3] + (1.f - c1) * acc0[j][3];
                    *(float2*)(out + (size_t)gn1 * 128 + col) = r;
                }
            }
        }
    }
}

// ---------------- launch ----------------
// k_node stays 4th (the ncu capture window) — clean A/B vs R8's conflicted profile.
extern "C" void kernel_launch(void* const* d_in, const int* in_sizes, int n_in,
                              void* d_out, int out_size) {
    const float* x    = (const float*)d_in[0];
    const float* Wt0  = (const float*)d_in[2];
    const float* bt0  = (const float*)d_in[3];
    const float* Wt1  = (const float*)d_in[4];
    const float* bt1  = (const float*)d_in[5];
    const float* gW   = (const float*)d_in[6];
    const float* atts = (const float*)d_in[7];
    const float* attd = (const float*)d_in[8];
    const float* gbias= (const float*)d_in[9];
    const float* gnw  = (const float*)d_in[10];
    const float* gnb  = (const float*)d_in[11];
    const float* gnms = (const float*)d_in[12];
    const float* Wc0  = (const float*)d_in[13];
    const float* bc0  = (const float*)d_in[14];
    const float* Wc1  = (const float*)d_in[15];
    const float* bc1  = (const float*)d_in[16];
    const void*  ei   = d_in[17];
    const void*  mask = d_in[18];
    float* out = (float*)d_out;

    cudaFuncSetAttribute(k_node,  cudaFuncAttributeMaxDynamicSharedMemorySize, SMEM_NODE);
    cudaFuncSetAttribute(k_final, cudaFuncAttributeMaxDynamicSharedMemorySize, SMEM_FINAL);

    const int NB_SCAN = (N_ + 1023) / 1024;

    k_detect   <<<1, 32>>>(ei, mask);
    k_wsplit   <<<224, 256>>>(Wt1, Wt0, gW, Wc1, Wc0);
    k_zero     <<<(N_ + 255) / 256, 256>>>();
    k_node     <<<(N_ + 63) / 64, 256, SMEM_NODE>>>(x, bt0, bt1, atts, attd, mask);
    k_hist     <<<(E_ + 255) / 256, 256>>>(ei);
    k_scan1    <<<NB_SCAN, 1024>>>();
    k_scan2    <<<1, 32>>>(NB_SCAN);
    k_scan3    <<<NB_SCAN, 1024>>>();
    k_fillself <<<(N_ + 255) / 256, 256>>>();
    k_filledges<<<(E_ + 255) / 256, 256>>>(ei);
    k_gat      <<<(N_ + 7) / 8, 256>>>(gbias);
    k_stats    <<<1, 128>>>(gnw, gnb, gnms);
    k_final    <<<(N_ + 63) / 64, 512, SMEM_FINAL>>>(x, bc0, bc1, mask, out);
}